// round 13
// baseline (speedup 1.0000x reference)
#include <cuda_runtime.h>
#include <cuda_bf16.h>
#include <math.h>

#define SEQL   2048
#define BATCH  2
#define DMODEL 1024
#define NHEADS 16
#define DHEAD  64
#define MR     (BATCH * SEQL)   // 4096 rows
#define NSEG   16
#define SEGROWS (SEQL / NSEG)   // 128
#define KP     (DMODEL / 2)     // 512 bf16-pair columns

// ---------------- scratch ----------------
__device__ float    g_Q[(size_t)MR * DMODEL];
__device__ float    g_K[(size_t)MR * DMODEL];
__device__ float    g_V[(size_t)MR * DMODEL];
__device__ float    g_Xr[(size_t)MR * DMODEL];         // tf32-rounded X (x1 path)
__device__ float    g_Wr[(size_t)2 * DMODEL * DMODEL]; // Wq then Wk, rounded
__device__ unsigned g_Qt[(size_t)MR * DMODEL];         // tf32 hi bits, PRE-SCALED by 0.125
__device__ unsigned g_Kt[(size_t)MR * DMODEL];
__device__ unsigned g_Xh[(size_t)MR * KP];
__device__ unsigned g_Xl[(size_t)MR * KP];
__device__ unsigned g_Wvh[(size_t)DMODEL * KP];
__device__ unsigned g_Wvl[(size_t)DMODEL * KP];
__device__ unsigned g_Woh[(size_t)DMODEL * KP];
__device__ unsigned g_Wol[(size_t)DMODEL * KP];
__device__ unsigned g_Vth[(size_t)BATCH * NHEADS * DHEAD * (SEQL / 2)];
__device__ unsigned g_Vtl[(size_t)BATCH * NHEADS * DHEAD * (SEQL / 2)];
__device__ unsigned g_Oh[(size_t)MR * KP];
__device__ unsigned g_Ol[(size_t)MR * KP];
__device__ float    g_F[(size_t)BATCH * SEQL * SEQL];
__device__ float    g_P[(size_t)BATCH * NSEG * SEQL];

// ---------------- helpers ----------------
__device__ __forceinline__ unsigned f2t(float x) {
    unsigned r;
    asm("cvt.rna.tf32.f32 %0, %1;" : "=r"(r) : "f"(x));
    return r;
}

__device__ __forceinline__ void bsplit(float x0, float x1, unsigned& h, unsigned& l) {
    asm("cvt.rn.bf16x2.f32 %0, %1, %2;" : "=r"(h) : "f"(x1), "f"(x0));
    __nv_bfloat162 hb = *reinterpret_cast<__nv_bfloat162*>(&h);
    float2 hf = __bfloat1622float2(hb);
    float r0 = x0 - hf.x, r1 = x1 - hf.y;
    asm("cvt.rn.bf16x2.f32 %0, %1, %2;" : "=r"(l) : "f"(r1), "f"(r0));
}

__device__ __forceinline__ void cpa16(void* smem, const void* gmem) {
    unsigned s = (unsigned)__cvta_generic_to_shared(smem);
    asm volatile("cp.async.cg.shared.global [%0], [%1], 16;" :: "r"(s), "l"(gmem));
}
#define CP_COMMIT() asm volatile("cp.async.commit_group;")
#define CP_WAIT1()  asm volatile("cp.async.wait_group 1;")
#define CP_WAIT0()  asm volatile("cp.async.wait_group 0;")

#define MMA(C, A0, A1, A2, A3, B0, B1)                                         \
    asm volatile(                                                              \
        "mma.sync.aligned.m16n8k8.row.col.f32.tf32.tf32.f32 "                  \
        "{%0,%1,%2,%3},{%4,%5,%6,%7},{%8,%9},{%0,%1,%2,%3};"                   \
        : "+f"((C)[0]), "+f"((C)[1]), "+f"((C)[2]), "+f"((C)[3])               \
        : "r"(A0), "r"(A1), "r"(A2), "r"(A3), "r"(B0), "r"(B1))

#define MMAB(C, A0, A1, A2, A3, B0, B1)                                        \
    asm volatile(                                                              \
        "mma.sync.aligned.m16n8k16.row.col.f32.bf16.bf16.f32 "                 \
        "{%0,%1,%2,%3},{%4,%5,%6,%7},{%8,%9},{%0,%1,%2,%3};"                   \
        : "+f"((C)[0]), "+f"((C)[1]), "+f"((C)[2]), "+f"((C)[3])               \
        : "r"(A0), "r"(A1), "r"(A2), "r"(A3), "r"(B0), "r"(B1))

// ---------------- mega prepass: all operand splits/rounds in ONE launch --------------
#define PRE_N0 (MR * KP)
#define PRE_N1 (DMODEL * KP)
#define PRE_TOT (PRE_N0 + 4 * PRE_N1)

__global__ __launch_bounds__(256) void prepass(const float* __restrict__ X,
                                               const float* __restrict__ Wv,
                                               const float* __restrict__ Wo,
                                               const float* __restrict__ Wq,
                                               const float* __restrict__ Wk) {
    int i = blockIdx.x * 256 + threadIdx.x;
    if (i < PRE_N0) {
        float2 v = ((const float2*)X)[i];
        unsigned hh, ll;
        bsplit(v.x, v.y, hh, ll);
        g_Xh[i] = hh;
        g_Xl[i] = ll;
        float2 o;
        o.x = __uint_as_float(f2t(v.x));
        o.y = __uint_as_float(f2t(v.y));
        ((float2*)g_Xr)[i] = o;
        return;
    }
    i -= PRE_N0;
    if (i < PRE_N1) {
        float2 v = ((const float2*)Wv)[i];
        unsigned hh, ll;
        bsplit(v.x, v.y, hh, ll);
        g_Wvh[i] = hh;
        g_Wvl[i] = ll;
        return;
    }
    i -= PRE_N1;
    if (i < PRE_N1) {
        float2 v = ((const float2*)Wo)[i];
        unsigned hh, ll;
        bsplit(v.x, v.y, hh, ll);
        g_Woh[i] = hh;
        g_Wol[i] = ll;
        return;
    }
    i -= PRE_N1;
    if (i < PRE_N1) {
        float2 v = ((const float2*)Wq)[i];
        float2 o;
        o.x = __uint_as_float(f2t(v.x));
        o.y = __uint_as_float(f2t(v.y));
        ((float2*)g_Wr)[i] = o;
        return;
    }
    i -= PRE_N1;
    if (i < PRE_N1) {
        float2 v = ((const float2*)Wk)[i];
        float2 o;
        o.x = __uint_as_float(f2t(v.x));
        o.y = __uint_as_float(f2t(v.y));
        ((float2*)(g_Wr + (size_t)DMODEL * DMODEL))[i] = o;
    }
}

// ---------------- qk tile body (BK=32, 2-stage, mixed split) ----------------
#define QK_SS   (128 * 36)

template <int SPLIT>
__device__ __forceinline__ void qk_body(const float* __restrict__ Asrc,
                                        const float* __restrict__ Bsrc,
                                        float* __restrict__ Y,
                                        int m0, int col0,
                                        float* __restrict__ Asm,
                                        float* __restrict__ Bsm) {
    const int tid = threadIdx.x, lane = tid & 31, warp = tid >> 5;
    const int g = lane >> 2, tg = lane & 3;
    const int wm = warp >> 2, wn = warp & 3;

    float c[4][4][4] = {};

#define QK_LOAD(stage, k0)                                                     \
    do {                                                                       \
        float* As_ = Asm + (stage) * QK_SS;                                    \
        float* Bs_ = Bsm + (stage) * QK_SS;                                    \
        _Pragma("unroll")                                                      \
        for (int t = 0; t < 4; t++) {                                          \
            int idx = tid + t * 256;                                           \
            int r = idx >> 3, c4 = (idx & 7) * 4;                              \
            cpa16(&As_[r * 36 + c4], &Asrc[(size_t)r * DMODEL + (k0) + c4]);   \
            cpa16(&Bs_[r * 36 + c4], &Bsrc[(size_t)r * DMODEL + (k0) + c4]);   \
        }                                                                      \
    } while (0)

    QK_LOAD(0, 0);
    CP_COMMIT();

    const int nIt = DMODEL / 32;
    for (int it = 0; it < nIt; it++) {
        const int st = it & 1;
        if (it + 1 < nIt) {
            QK_LOAD(st ^ 1, (it + 1) * 32);
            CP_COMMIT();
            CP_WAIT1();
        } else {
            CP_WAIT0();
        }
        __syncthreads();

        const float* As_ = Asm + st * QK_SS;
        const float* Bs_ = Bsm + st * QK_SS;
#pragma unroll
        for (int kc = 0; kc < 4; kc++) {
            unsigned bh[4][2], bl[4][2];
#pragma unroll
            for (int ni = 0; ni < 4; ni++) {
                int nb = (wn * 32 + ni * 8 + g) * 36 + kc * 8 + tg;
                float b0 = Bs_[nb];
                float b1 = Bs_[nb + 4];
                if (SPLIT == 3) {
                    bh[ni][0] = f2t(b0);
                    bh[ni][1] = f2t(b1);
                    bl[ni][0] = f2t(b0 - __uint_as_float(bh[ni][0]));
                    bl[ni][1] = f2t(b1 - __uint_as_float(bh[ni][1]));
                } else {
                    bh[ni][0] = __float_as_uint(b0);
                    bh[ni][1] = __float_as_uint(b1);
                }
            }
#pragma unroll
            for (int mi = 0; mi < 4; mi++) {
                int r1 = (wm * 64 + mi * 16 + g) * 36 + kc * 8 + tg;
                int r2 = r1 + 8 * 36;
                float a0 = As_[r1];
                float a1 = As_[r2];
                float a2 = As_[r1 + 4];
                float a3 = As_[r2 + 4];
                unsigned ah0, ah1, ah2, ah3;
                unsigned al0 = 0, al1 = 0, al2 = 0, al3 = 0;
                if (SPLIT == 3) {
                    ah0 = f2t(a0); ah1 = f2t(a1); ah2 = f2t(a2); ah3 = f2t(a3);
                    al0 = f2t(a0 - __uint_as_float(ah0));
                    al1 = f2t(a1 - __uint_as_float(ah1));
                    al2 = f2t(a2 - __uint_as_float(ah2));
                    al3 = f2t(a3 - __uint_as_float(ah3));
                } else {
                    ah0 = __float_as_uint(a0); ah1 = __float_as_uint(a1);
                    ah2 = __float_as_uint(a2); ah3 = __float_as_uint(a3);
                }
#pragma unroll
                for (int ni = 0; ni < 4; ni++) {
                    MMA(c[mi][ni], ah0, ah1, ah2, ah3, bh[ni][0], bh[ni][1]);
                    if (SPLIT == 3) {
                        MMA(c[mi][ni], ah0, ah1, ah2, ah3, bl[ni][0], bl[ni][1]);
                        MMA(c[mi][ni], al0, al1, al2, al3, bh[ni][0], bh[ni][1]);
                    }
                }
            }
        }
        __syncthreads();
    }
#undef QK_LOAD

#pragma unroll
    for (int mi = 0; mi < 4; mi++)
#pragma unroll
        for (int ni = 0; ni < 4; ni++) {
            int r = m0 + wm * 64 + mi * 16 + g;
            int col = col0 + wn * 32 + ni * 8 + 2 * tg;
            *(float2*)&Y[(size_t)r * DMODEL + col] = make_float2(c[mi][ni][0], c[mi][ni][1]);
            *(float2*)&Y[(size_t)(r + 8) * DMODEL + col] = make_float2(c[mi][ni][2], c[mi][ni][3]);
        }
}

// ---------------- bf16x3 tile body (BK=16 pairs, 2-stage) ----------------
__device__ __forceinline__ void bf3_body(const unsigned* __restrict__ Ah,
                                         const unsigned* __restrict__ Al,
                                         const unsigned* __restrict__ Bh,
                                         const unsigned* __restrict__ Bl,
                                         float* __restrict__ Y,
                                         int m0, int n0, int N, int Kp,
                                         unsigned* __restrict__ dsm) {
    const int AS = 128 * 20;
    const int tid = threadIdx.x, lane = tid & 31, warp = tid >> 5;
    const int g = lane >> 2, tg = lane & 3;
    const int wm = warp >> 2, wn = warp & 3;
    const int lr = tid >> 2, lc = (tid & 3) * 4;

    float c[4][4][4] = {};

    {
        unsigned* base = dsm;
#pragma unroll
        for (int t = 0; t < 2; t++) {
            int r = lr + t * 64;
            cpa16(&base[0 * AS + r * 20 + lc], &Ah[(size_t)(m0 + r) * Kp + lc]);
            cpa16(&base[1 * AS + r * 20 + lc], &Al[(size_t)(m0 + r) * Kp + lc]);
            cpa16(&base[2 * AS + r * 20 + lc], &Bh[(size_t)(n0 + r) * Kp + lc]);
            cpa16(&base[3 * AS + r * 20 + lc], &Bl[(size_t)(n0 + r) * Kp + lc]);
        }
        CP_COMMIT();
    }

    const int nIt = Kp / 16;
    for (int it = 0; it < nIt; it++) {
        const int st = it & 1;
        if (it + 1 < nIt) {
            const int k0 = (it + 1) * 16;
            unsigned* base = dsm + (st ^ 1) * 4 * AS;
#pragma unroll
            for (int t = 0; t < 2; t++) {
                int r = lr + t * 64;
                cpa16(&base[0 * AS + r * 20 + lc], &Ah[(size_t)(m0 + r) * Kp + k0 + lc]);
                cpa16(&base[1 * AS + r * 20 + lc], &Al[(size_t)(m0 + r) * Kp + k0 + lc]);
                cpa16(&base[2 * AS + r * 20 + lc], &Bh[(size_t)(n0 + r) * Kp + k0 + lc]);
                cpa16(&base[3 * AS + r * 20 + lc], &Bl[(size_t)(n0 + r) * Kp + k0 + lc]);
            }
            CP_COMMIT();
            CP_WAIT1();
        } else {
            CP_WAIT0();
        }
        __syncthreads();

        unsigned* sAh = dsm + st * 4 * AS;
        unsigned* sAl = sAh + AS;
        unsigned* sBh = sAh + 2 * AS;
        unsigned* sBl = sAh + 3 * AS;
#pragma unroll
        for (int kc = 0; kc < 2; kc++) {
            unsigned bhf[4][2], blf[4][2];
#pragma unroll
            for (int ni = 0; ni < 4; ni++) {
                int nb = (wn * 32 + ni * 8 + g) * 20 + kc * 8 + tg;
                bhf[ni][0] = sBh[nb];
                bhf[ni][1] = sBh[nb + 4];
                blf[ni][0] = sBl[nb];
                blf[ni][1] = sBl[nb + 4];
            }
#pragma unroll
            for (int mi = 0; mi < 4; mi++) {
                int r1 = (wm * 64 + mi * 16 + g) * 20 + kc * 8 + tg;
                int r2 = r1 + 8 * 20;
                unsigned ah0 = sAh[r1], ah1 = sAh[r2], ah2 = sAh[r1 + 4], ah3 = sAh[r2 + 4];
                unsigned al0 = sAl[r1], al1 = sAl[r2], al2 = sAl[r1 + 4], al3 = sAl[r2 + 4];
#pragma unroll
                for (int ni = 0; ni < 4; ni++) {
                    MMAB(c[mi][ni], ah0, ah1, ah2, ah3, bhf[ni][0], bhf[ni][1]);
                    MMAB(c[mi][ni], ah0, ah1, ah2, ah3, blf[ni][0], blf[ni][1]);
                    MMAB(c[mi][ni], al0, al1, al2, al3, bhf[ni][0], bhf[ni][1]);
                }
            }
        }
        __syncthreads();
    }

#pragma unroll
    for (int mi = 0; mi < 4; mi++)
#pragma unroll
        for (int ni = 0; ni < 4; ni++) {
            int r = m0 + wm * 64 + mi * 16 + g;
            int col = n0 + wn * 32 + ni * 8 + 2 * tg;
            *(float2*)&Y[(size_t)r * N + col] = make_float2(c[mi][ni][0], c[mi][ni][1]);
            *(float2*)&Y[(size_t)(r + 8) * N + col] = make_float2(c[mi][ni][2], c[mi][ni][3]);
        }
}

// ---------------- fused projections: QK (mixed tf32) + V (bf16x3) ----------
#define PROJ_SMEM (2 * 4 * 128 * 20 * 4)   // 81920 B

__global__ __launch_bounds__(256) void proj_fused(const float* __restrict__ X,
                                                  const float* __restrict__ Wq,
                                                  const float* __restrict__ Wk,
                                                  const float* __restrict__ Xr,
                                                  const float* __restrict__ Wr,
                                                  float* __restrict__ Q,
                                                  float* __restrict__ K,
                                                  float* __restrict__ V) {
    extern __shared__ float fsm[];
    const int xt = blockIdx.x;
    const int m0 = blockIdx.y * 128;

    if (xt < 16) {
        float* Asm = fsm;
        float* Bsm = fsm + 2 * QK_SS;
        float* Y = (xt < 8) ? Q : K;
        const int col0 = (xt & 7) * 128;
        if (xt == 0 || xt == 8) {
            const float* Asrc = X + (size_t)m0 * DMODEL;
            const float* Bsrc = (xt < 8) ? Wq : Wk;
            qk_body<3>(Asrc, Bsrc, Y, m0, col0, Asm, Bsm);
        } else {
            const float* Asrc = Xr + (size_t)m0 * DMODEL;
            const float* Bsrc = Wr + (size_t)xt * 128 * DMODEL;
            qk_body<1>(Asrc, Bsrc, Y, m0, col0, Asm, Bsm);
        }
    } else {
        bf3_body(g_Xh, g_Xl, g_Wvh, g_Wvl, V, m0, (xt - 16) * 128, DMODEL, KP,
                 (unsigned*)fsm);
    }
}

// ---------------- standalone bf16x3 GEMM (output projection) ----------
__global__ __launch_bounds__(256) void gemm_bf3(const unsigned* __restrict__ Ah,
                                                const unsigned* __restrict__ Al,
                                                const unsigned* __restrict__ Bh,
                                                const unsigned* __restrict__ Bl,
                                                float* __restrict__ Y,
                                                int M, int N, int Kp) {
    extern __shared__ unsigned dsm[];
    bf3_body(Ah, Al, Bh, Bl, Y, blockIdx.y * 128, blockIdx.x * 128, N, Kp, dsm);
}

// ---------------- stitched LN(Q) + LN(K) + V-transpose/split ----------------
__device__ __forceinline__ void ln_body(float* __restrict__ y,
                                        const float* __restrict__ g,
                                        const float* __restrict__ b,
                                        unsigned* __restrict__ t,
                                        float scale, float* red) {
    float s = 0.f;
    for (int i = threadIdx.x; i < DMODEL; i += 256) s += y[i];
    red[threadIdx.x] = s;
    __syncthreads();
    for (int o = 128; o > 0; o >>= 1) {
        if (threadIdx.x < o) red[threadIdx.x] += red[threadIdx.x + o];
        __syncthreads();
    }
    const float mu = red[0] * (1.0f / DMODEL);
    __syncthreads();

    float v = 0.f;
    for (int i = threadIdx.x; i < DMODEL; i += 256) {
        float d = y[i] - mu;
        v += d * d;
    }
    red[threadIdx.x] = v;
    __syncthreads();
    for (int o = 128; o > 0; o >>= 1) {
        if (threadIdx.x < o) red[threadIdx.x] += red[threadIdx.x + o];
        __syncthreads();
    }
    const float rstd = rsqrtf(red[0] * (1.0f / DMODEL) + 1e-5f);
    __syncthreads();

    for (int i = threadIdx.x; i < DMODEL; i += 256) {
        float val = (y[i] - mu) * rstd * g[i] + b[i];
        y[i] = val;
        t[i] = f2t(val * scale);
    }
}

__global__ __launch_bounds__(256) void ln_vt(float* __restrict__ Q,
                                             float* __restrict__ K,
                                             const float* __restrict__ gq,
                                             const float* __restrict__ bq,
                                             const float* __restrict__ gk,
                                             const float* __restrict__ bk) {
    __shared__ float buf[64 * 68];    // 17.4 KB: vt tile; ln uses first 256 floats
    int blk = blockIdx.x;
    if (blk < MR) {
        ln_body(g_Q + (size_t)blk * DMODEL, gq, bq, g_Qt + (size_t)blk * DMODEL,
                0.125f, buf);
        return;
    }
    blk -= MR;
    if (blk < MR) {
        ln_body(g_K + (size_t)blk * DMODEL, gk, bk, g_Kt + (size_t)blk * DMODEL,
                1.0f, buf);
        return;
    }
    blk -= MR;
    // vt_split block: blk in [0, 1024)
    const int nt = blk & 31, h = (blk >> 5) & 15, b = blk >> 9;
    const int n0 = nt * 64;
    const int tid = threadIdx.x;
    float (*tile)[68] = (float(*)[68])buf;
#pragma unroll
    for (int t = 0; t < 4; t++) {
        int idx = tid + t * 256;
        int r = idx >> 4, c4 = (idx & 15) * 4;
        *(float4*)&tile[r][c4] =
            *(const float4*)&g_V[(size_t)(b * SEQL + n0 + r) * DMODEL + h * DHEAD + c4];
    }
    __syncthreads();
#pragma unroll
    for (int t = 0; t < 8; t++) {
        int idx = tid + t * 256;
        int d = idx >> 5, j = idx & 31;
        unsigned hh, ll;
        bsplit(tile[2 * j][d], tile[2 * j + 1][d], hh, ll);
        size_t off = ((size_t)((b * NHEADS + h) * DHEAD + d)) * (SEQL / 2) + (n0 >> 1) + j;
        g_Vth[off] = hh;
        g_Vtl[off] = ll;
    }
}

// ---------------- head-0 scores + FUSED segment column-sums ----------------
__global__ __launch_bounds__(256) void head0_tc() {
    __shared__ float As[128][36];
    __shared__ float Bs[128][36];
    __shared__ float cs[128];
    const int tid = threadIdx.x, lane = tid & 31, warp = tid >> 5;
    const int g = lane >> 2, tg = lane & 3;
    const int wm = warp >> 2, wn = warp & 3;
    const int bb = blockIdx.z;
    const int r0 = blockIdx.y * 128, mm0 = blockIdx.x * 128;
    const size_t pbase = (size_t)(bb * NSEG + blockIdx.y) * SEQL + mm0;

    if (mm0 >= r0 + 128) {   // strictly upper-triangle: C = 0, P-partial = 0
        const float2 z = make_float2(0.f, 0.f);
#pragma unroll
        for (int mi = 0; mi < 4; mi++)
#pragma unroll
            for (int ni = 0; ni < 4; ni++) {
                int r1 = r0 + wm * 64 + mi * 16 + g;
                int m = mm0 + wn * 32 + ni * 8 + 2 * tg;
                *(float2*)&g_F[(size_t)(bb * SEQL + r1) * SEQL + m] = z;
                *(float2*)&g_F[(size_t)(bb * SEQL + r1 + 8) * SEQL + m] = z;
            }
        if (tid < 128) g_P[pbase + tid] = 0.f;
        return;
    }

    const float* Aq = g_Q + (size_t)(bb * SEQL + r0) * DMODEL;
    const float* Bk = g_K + (size_t)(bb * SEQL + mm0) * DMODEL;
    const int lrow = tid >> 3, lcol = (tid & 7) * 4;

    float c[4][4][4] = {};

    for (int k0 = 0; k0 < 64; k0 += 32) {
#pragma unroll
        for (int it = 0; it < 4; it++) {
            int r = lrow + it * 32;
            *(float4*)&As[r][lcol] = *(const float4*)&Aq[(size_t)r * DMODEL + k0 + lcol];
            *(float4*)&Bs[r][lcol] = *(const float4*)&Bk[(size_t)r * DMODEL + k0 + lcol];
        }
        __syncthreads();
#pragma unroll
        for (int kc = 0; kc < 4; kc++) {
            unsigned bh[4][2], bl[4][2];
#pragma unroll
            for (int ni = 0; ni < 4; ni++) {
                int nb = wn * 32 + ni * 8;
                float b0 = Bs[nb + g][kc * 8 + tg];
                float b1 = Bs[nb + g][kc * 8 + tg + 4];
                bh[ni][0] = f2t(b0);
                bh[ni][1] = f2t(b1);
                bl[ni][0] = f2t(b0 - __uint_as_float(bh[ni][0]));
                bl[ni][1] = f2t(b1 - __uint_as_float(bh[ni][1]));
            }
#pragma unroll
            for (int mi = 0; mi < 4; mi++) {
                int rm = wm * 64 + mi * 16;
                float a0 = As[rm + g][kc * 8 + tg];
                float a1 = As[rm + g + 8][kc * 8 + tg];
                float a2 = As[rm + g][kc * 8 + tg + 4];
                float a3 = As[rm + g + 8][kc * 8 + tg + 4];
                unsigned ah0 = f2t(a0), ah1 = f2t(a1), ah2 = f2t(a2), ah3 = f2t(a3);
                unsigned al0 = f2t(a0 - __uint_as_float(ah0));
                unsigned al1 = f2t(a1 - __uint_as_float(ah1));
                unsigned al2 = f2t(a2 - __uint_as_float(ah2));
                unsigned al3 = f2t(a3 - __uint_as_float(ah3));
#pragma unroll
                for (int ni = 0; ni < 4; ni++) {
                    MMA(c[mi][ni], ah0, ah1, ah2, ah3, bh[ni][0], bh[ni][1]);
                    MMA(c[mi][ni], ah0, ah1, ah2, ah3, bl[ni][0], bl[ni][1]);
                    MMA(c[mi][ni], al0, al1, al2, al3, bh[ni][0], bh[ni][1]);
                }
            }
        }
        __syncthreads();
    }

    if (tid < 128) cs[tid] = 0.f;
    __syncthreads();

    float csl[4][2] = {};
#pragma unroll
    for (int mi = 0; mi < 4; mi++)
#pragma unroll
        for (int ni = 0; ni < 4; ni++) {
            int r1 = r0 + wm * 64 + mi * 16 + g;
            int r2 = r1 + 8;
            int m = mm0 + wn * 32 + ni * 8 + 2 * tg;
            float v0 = c[mi][ni][0] * 0.125f;
            float v1 = c[mi][ni][1] * 0.125f;
            float v2 = c[mi][ni][2] * 0.125f;
            float v3 = c[mi][ni][3] * 0.125f;
            v0 = (m >= 1 && m < r1) ? fmaxf(v0, 0.f) : 0.f;
            v1 = (m + 1 < r1) ? fmaxf(v1, 0.f) : 0.f;
            v2 = (m >= 1 && m < r2) ? fmaxf(v2, 0.f) : 0.f;
            v3 = (m + 1 < r2) ? fmaxf(v3, 0.f) : 0.f;
            *(float2*)&g_F[(size_t)(bb * SEQL + r1) * SEQL + m] = make_float2(v0, v1);
            *(float2*)&g_F[(size_t)(bb * SEQL + r2) * SEQL + m] = make_float2(v2, v3);
            csl[ni][0] += v0 + v2;
            csl[ni][1] += v1 + v3;
        }

    // reduce over the 8 g-lanes (xor 4,8,16 move only g bits)
#pragma unroll
    for (int ni = 0; ni < 4; ni++)
#pragma unroll
        for (int j = 0; j < 2; j++) {
            float v = csl[ni][j];
            v += __shfl_xor_sync(0xffffffffu, v, 4);
            v += __shfl_xor_sync(0xffffffffu, v, 8);
            v += __shfl_xor_sync(0xffffffffu, v, 16);
            csl[ni][j] = v;
        }
    if (g == 0) {    // one lane per tg holds the warp's column sums
#pragma unroll
        for (int ni = 0; ni < 4; ni++) {
            atomicAdd(&cs[wn * 32 + ni * 8 + 2 * tg], csl[ni][0]);
            atomicAdd(&cs[wn * 32 + ni * 8 + 2 * tg + 1], csl[ni][1]);
        }
    }
    __syncthreads();
    if (tid < 128) g_P[pbase + tid] = cs[tid];
}

// ---------------- 2 remaining scan passes ----------------
__global__ __launch_bounds__(256) void seg_scan() {
    const int m = blockIdx.x * 256 + threadIdx.x;
    const int b = blockIdx.y;
    float acc = 0.f;
#pragma unroll
    for (int s = 0; s < NSEG; s++) {
        size_t idx = (size_t)(b * NSEG + s) * SEQL + m;
        float v = g_P[idx];
        g_P[idx] = acc;
        acc += v;
    }
}

__global__ __launch_bounds__(256) void final_scan() {
    const int m = blockIdx.x * 256 + threadIdx.x;
    const int seg = blockIdx.y, b = blockIdx.z;
    float acc = g_P[(size_t)(b * NSEG + seg) * SEQL + m];
    float* base = g_F + (size_t)(b * SEQL + seg * SEGROWS) * SEQL + m;
#pragma unroll 4
    for (int r = 0; r < SEGROWS; r++) {
        float c = base[(size_t)r * SEQL];
        base[(size_t)r * SEQL] = acc;
        acc += c;
    }
}

// ---------------- flash attention: BM=64, 128 threads, cp.async K/V ----------
#define ATTN_KSZ  (64 * 68)
#define ATTN_VSZ  (64 * 36)
#define ATTN_VHOFF (2 * ATTN_KSZ)
#define ATTN_VLOFF (2 * ATTN_KSZ + 2 * ATTN_VSZ)
#define ATTN_SMEM  ((2 * ATTN_KSZ + 4 * ATTN_VSZ) * 4)

__global__ __launch_bounds__(128) void attn_bf() {
    extern __shared__ unsigned sm[];
    const int b = blockIdx.z, h = blockIdx.y;
    const int qt = (int)gridDim.x - 1 - (int)blockIdx.x;
    const int q0 = qt * 64;
    const int tid = threadIdx.x, lane = tid & 31, w = tid >> 5;
    const int g = lane >> 2, tg = lane & 3;

    unsigned qa[8][4];
    const size_t qr1 = (size_t)(b * SEQL + q0 + w * 16 + g) * DMODEL + h * DHEAD;
    const size_t qr2 = qr1 + 8 * DMODEL;
#pragma unroll
    for (int kc = 0; kc < 8; kc++) {
        qa[kc][0] = g_Qt[qr1 + kc * 8 + tg];
        qa[kc][1] = g_Qt[qr2 + kc * 8 + tg];
        qa[kc][2] = g_Qt[qr1 + kc * 8 + tg + 4];
        qa[kc][3] = g_Qt[qr2 + kc * 8 + tg + 4];
    }

    float o[8][4] = {};
    float qm0 = -1e30f, qm1 = -1e30f, lsum0 = 0.f, lsum1 = 0.f;

    {
        const size_t kbase = (size_t)(b * SEQL) * DMODEL + h * DHEAD;
        const size_t vbase = (size_t)((b * NHEADS + h) * DHEAD) * (SEQL / 2);
#pragma unroll
        for (int t = 0; t < 8; t++) {
            int idx = tid + t * 128;
            int r = idx >> 4, c4 = (idx & 15) * 4;
            cpa16(&sm[r * 68 + c4], &g_Kt[kbase + (size_t)r * DMODEL + c4]);
        }
#pragma unroll
        for (int t = 0; t < 4; t++) {
            int idx = tid + t * 128;
            int r = idx >> 3, c4 = (idx & 7) * 4;
            cpa16(&sm[ATTN_VHOFF + r * 36 + c4], &g_Vth[vbase + (size_t)r * (SEQL / 2) + c4]);
            cpa16(&sm[ATTN_VLOFF + r * 36 + c4], &g_Vtl[vbase + (size_t)r * (SEQL / 2) + c4]);
        }
        CP_COMMIT();
    }

    for (int kt = 0; kt <= qt; kt++) {
        const int buf = kt & 1;
        const int m0 = kt * 64;
        if (kt < qt) {
            const int m0n = m0 + 64;
            const int nb = buf ^ 1;
            const size_t kbase = (size_t)(b * SEQL + m0n) * DMODEL + h * DHEAD;
            const size_t vbase = (size_t)((b * NHEADS + h) * DHEAD) * (SEQL / 2) + (m0n >> 1);
#pragma unroll
            for (int t = 0; t < 8; t++) {
                int idx = tid + t * 128;
                int r = idx >> 4, c4 = (idx & 15) * 4;
                cpa16(&sm[nb * ATTN_KSZ + r * 68 + c4], &g_Kt[kbase + (size_t)r * DMODEL + c4]);
            }
#pragma unroll
            for (int t = 0; t < 4; t++) {
                int idx = tid + t * 128;
                int r = idx >> 3, c4 = (idx & 7) * 4;
                cpa16(&sm[ATTN_VHOFF + nb * ATTN_VSZ + r * 36 + c4],
                      &g_Vth[vbase + (size_t)r * (SEQL / 2) + c4]);
                cpa16(&sm[ATTN_VLOFF + nb * ATTN_VSZ + r * 36 + c4],
                      &g_Vtl[vbase + (size_t)r * (SEQL / 2) + c4]);
            }
            CP_COMMIT();
            CP_WAIT1();
        } else {
            CP_WAIT0();
        }
        __syncthreads();

        const unsigned* sKt = sm + buf * ATTN_KSZ;
        const unsigned* sVh = sm + ATTN_VHOFF + buf * ATTN_VSZ;
        const unsigned* sVl = sm + ATTN_VLOFF + buf * ATTN_VSZ;

        float sc[8][4] = {};
#pragma unroll
        for (int kc = 0; kc < 8; kc++) {
#pragma unroll
            for (int ni = 0; ni < 8; ni++) {
                unsigned b0 = sKt[(ni * 8 + g) * 68 + kc * 8 + tg];
                unsigned b1 = sKt[(ni * 8 + g) * 68 + kc * 8 + tg + 4];
                MMA(sc[ni], qa[kc][0], qa[kc][1], qa[kc][2], qa[kc][3], b0, b1);
            }
        }

        const bool diag = (kt == qt);
        const int lr1 = w * 16 + g, lr2 = lr1 + 8;
        const size_t frow1 = (size_t)(b * SEQL + q0 + lr1) * SEQL + m0;
        const size_t frow2 = (size_t)(b * SEQL + q0 + lr2) * SEQL + m0;
        float mx0 = -1e30f, mx1 = -1e30f;
#pragma unroll
        for (int ni = 0; ni < 8; ni++) {
            int cl = ni * 8 + 2 * tg;
            float2 f1 = *(const float2*)&g_F[frow1 + cl];
            float2 f2 = *(const float2*)&g_F[frow2 + cl];
            float v0 = sc[ni][0] - f1.x;
            float v1 = sc[ni][1] - f1.y;
            float v2 = sc[ni][2] - f2.x;
            float v3 = sc[ni][3] - f2.y;
            if (diag) {
                if (cl > lr1) v0 = -1e30f;
                if (cl + 1 > lr1) v1 = -1e30f;
                if (cl > lr2) v2 = -1e30f;
                if (cl + 1 > lr2) v3 = -1e30f;
            }
            sc[ni][0] = v0; sc[ni][1] = v1; sc[ni][2] = v2; sc[ni][3] = v3;
            mx0 = fmaxf(mx0, fmaxf(v0, v1));
            mx1 = fmaxf(mx1, fmaxf(v2, v3));
        }
        mx0 = fmaxf(mx0, __shfl_xor_sync(0xffffffffu, mx0, 1));
        mx0 = fmaxf(mx0, __shfl_xor_sync(0xffffffffu, mx0, 2));
        mx1 = fmaxf(mx1, __shfl_xor_sync(0xffffffffu, mx1, 1));
        mx1 = fmaxf(mx1, __shfl_xor_sync(0xffffffffu, mx1, 2));
        const float nm0 = fmaxf(qm0, mx0), nm1 = fmaxf(qm1, mx1);
        const float s0 = __expf(qm0 - nm0), s1 = __expf(qm1 - nm1);
        float ps0 = 0.f, ps1 = 0.f;
#pragma unroll
        for (int ni = 0; ni < 8; ni++) {
            float e0 = __expf(sc[ni][0] - nm0);
            float e1 = __expf(sc[ni][1] - nm0);
            float e2 = __expf(sc[ni][2] - nm1);
            float e3 = __expf(sc[ni][3] - nm1);
            sc[ni][0] = e0; sc[ni][1] = e1; sc[ni][2] = e2; sc[ni][3] = e3;
            ps0 += e0 + e1;
            ps1 += e2 + e3;
            o[ni][0] *= s0; o[ni][1] *= s0; o[ni][2] *= s1; o[ni][3] *= s1;
        }
        ps0 += __shfl_xor_sync(0xffffffffu, ps0, 1);
        ps0 += __shfl_xor_sync(0xffffffffu, ps0, 2);
        ps1 += __shfl_xor_sync(0xffffffffu, ps1, 1);
        ps1 += __shfl_xor_sync(0xffffffffu, ps1, 2);
        lsum0 = lsum0 * s0 + ps0;
        lsum1 = lsum1 * s1 + ps1;
        qm0 = nm0; qm1 = nm1;

#pragma unroll
        for (int kc2 = 0; kc2 < 4; kc2++) {
            unsigned ph0, pl0, ph1, pl1, ph2, pl2, ph3, pl3;
            bsplit(sc[kc2 * 2][0], sc[kc2 * 2][1], ph0, pl0);
            bsplit(sc[kc2 * 2][2], sc[kc2 * 2][3], ph1, pl1);
            bsplit(sc[kc2 * 2 + 1][0], sc[kc2 * 2 + 1][1], ph2, pl2);
            bsplit(sc[kc2 * 2 + 1][2], sc[kc2 * 2 + 1][3], ph3, pl3);
#pragma unroll
            for (int ni = 0; ni < 8; ni++) {
                int vb = (ni * 8 + g) * 36 + kc2 * 8 + tg;
                unsigned vh0 = sVh[vb], vh1 = sVh[vb + 4];
                unsigned vl0 = sVl[vb], vl1 = sVl[vb + 4];
                MMAB(o[ni], ph0, ph1, ph2, ph3, vh0, vh1);
                MMAB(o[ni], ph0, ph1, ph2, ph3, vl0, vl1);
                MMAB(o[ni], pl0, pl1, pl2, pl3, vh0, vh1);
            }
        }
        __syncthreads();
    }

    const float i0 = 1.0f / lsum0, i1 = 1.0f / lsum1;
    const size_t or1 = (size_t)(b * SEQL + q0 + w * 16 + g) * KP + h * 32;
    const size_t or2 = or1 + 8 * KP;
#pragma unroll
    for (int ni = 0; ni < 8; ni++) {
        unsigned hh, ll;
        bsplit(o[ni][0] * i0, o[ni][1] * i0, hh, ll);
        g_Oh[or1 + ni * 4 + tg] = hh;
        g_Ol[or1 + ni * 4 + tg] = ll;
        bsplit(o[ni][2] * i1, o[ni][3] * i1, hh, ll);
        g_Oh[or2 + ni * 4 + tg] = hh;
        g_Ol[or2 + ni * 4 + tg] = ll;
    }
}

// ---------------- launch ----------------
extern "C" void kernel_launch(void* const* d_in, const int* in_sizes, int n_in,
                              void* d_out, int out_size) {
    const float* X  = (const float*)d_in[0];
    const float* Wq = (const float*)d_in[1];
    const float* Wk = (const float*)d_in[2];
    const float* Wv = (const float*)d_in[3];
    const float* Wo = (const float*)d_in[4];
    const float* gq = (const float*)d_in[5];
    const float* bq = (const float*)d_in[6];
    const float* gk = (const float*)d_in[7];
    const float* bk = (const float*)d_in[8];
    float* out = (float*)d_out;

    float *pQ, *pK, *pV, *pXr, *pWr;
    unsigned *pWoh, *pWol, *pOh, *pOl;
    cudaGetSymbolAddress((void**)&pQ, g_Q);
    cudaGetSymbolAddress((void**)&pK, g_K);
    cudaGetSymbolAddress((void**)&pV, g_V);
    cudaGetSymbolAddress((void**)&pXr, g_Xr);
    cudaGetSymbolAddress((void**)&pWr, g_Wr);
    cudaGetSymbolAddress((void**)&pWoh, g_Woh);
    cudaGetSymbolAddress((void**)&pWol, g_Wol);
    cudaGetSymbolAddress((void**)&pOh, g_Oh);
    cudaGetSymbolAddress((void**)&pOl, g_Ol);

    cudaFuncSetAttribute(proj_fused, cudaFuncAttributeMaxDynamicSharedMemorySize, PROJ_SMEM);
    cudaFuncSetAttribute(gemm_bf3, cudaFuncAttributeMaxDynamicSharedMemorySize, PROJ_SMEM);
    cudaFuncSetAttribute(attn_bf, cudaFuncAttributeMaxDynamicSharedMemorySize, ATTN_SMEM);

    prepass<<<(PRE_TOT + 255) / 256, 256>>>(X, Wv, Wo, Wq, Wk);

    proj_fused<<<dim3(24, MR / 128), 256, PROJ_SMEM>>>(X, Wq, Wk, pXr, pWr, pQ, pK, pV);

    // LN(Q) + LN(K) + V transpose/split, one flat launch
    ln_vt<<<2 * MR + SEQL / 64 * NHEADS * BATCH, 256>>>(pQ, pK, gq, bq, gk, bk);

    // head0 scores + fused segment sums, then 2 scan passes
    head0_tc<<<dim3(SEQL / 128, SEQL / 128, BATCH), 256>>>();
    seg_scan<<<dim3(SEQL / 256, BATCH), 256>>>();
    final_scan<<<dim3(SEQL / 256, NSEG, BATCH), 256>>>();

    attn_bf<<<dim3(SEQL / 64, NHEADS, BATCH), 128, ATTN_SMEM>>>();

    gemm_bf3<<<dim3(DMODEL / 128, MR / 128), 256, PROJ_SMEM>>>(pOh, pOl, pWoh, pWol, out,
                                                               MR, DMODEL, KP);
}

// round 14
// speedup vs baseline: 1.0091x; 1.0091x over previous
#include <cuda_runtime.h>
#include <cuda_bf16.h>
#include <math.h>

#define SEQL   2048
#define BATCH  2
#define DMODEL 1024
#define NHEADS 16
#define DHEAD  64
#define MR     (BATCH * SEQL)   // 4096 rows
#define NSEG   16
#define SEGROWS (SEQL / NSEG)   // 128
#define KP     (DMODEL / 2)     // 512 bf16-pair columns

// ---------------- scratch ----------------
__device__ float    g_Q[(size_t)MR * DMODEL];
__device__ float    g_K[(size_t)MR * DMODEL];
__device__ float    g_V[(size_t)MR * DMODEL];
__device__ float    g_Xr[(size_t)MR * DMODEL];         // tf32-rounded X (x1 path)
__device__ float    g_Wr[(size_t)2 * DMODEL * DMODEL]; // Wq then Wk, rounded
__device__ unsigned g_Qt[(size_t)MR * DMODEL];         // tf32 hi bits, PRE-SCALED by 0.125
__device__ unsigned g_Kt[(size_t)MR * DMODEL];
__device__ unsigned g_Xh[(size_t)MR * KP];
__device__ unsigned g_Xl[(size_t)MR * KP];
__device__ unsigned g_Wvh[(size_t)DMODEL * KP];
__device__ unsigned g_Wvl[(size_t)DMODEL * KP];
__device__ unsigned g_Woh[(size_t)DMODEL * KP];
__device__ unsigned g_Wol[(size_t)DMODEL * KP];
__device__ unsigned g_Vth[(size_t)BATCH * NHEADS * DHEAD * (SEQL / 2)];
__device__ unsigned g_Vtl[(size_t)BATCH * NHEADS * DHEAD * (SEQL / 2)];
__device__ unsigned g_Oh[(size_t)MR * KP];
__device__ unsigned g_Ol[(size_t)MR * KP];
__device__ float    g_F[(size_t)BATCH * SEQL * SEQL];
__device__ float    g_P[(size_t)BATCH * NSEG * SEQL];

// ---------------- helpers ----------------
__device__ __forceinline__ unsigned f2t(float x) {
    unsigned r;
    asm("cvt.rna.tf32.f32 %0, %1;" : "=r"(r) : "f"(x));
    return r;
}

__device__ __forceinline__ void bsplit(float x0, float x1, unsigned& h, unsigned& l) {
    asm("cvt.rn.bf16x2.f32 %0, %1, %2;" : "=r"(h) : "f"(x1), "f"(x0));
    __nv_bfloat162 hb = *reinterpret_cast<__nv_bfloat162*>(&h);
    float2 hf = __bfloat1622float2(hb);
    float r0 = x0 - hf.x, r1 = x1 - hf.y;
    asm("cvt.rn.bf16x2.f32 %0, %1, %2;" : "=r"(l) : "f"(r1), "f"(r0));
}

__device__ __forceinline__ void cpa16(void* smem, const void* gmem) {
    unsigned s = (unsigned)__cvta_generic_to_shared(smem);
    asm volatile("cp.async.cg.shared.global [%0], [%1], 16;" :: "r"(s), "l"(gmem));
}
#define CP_COMMIT() asm volatile("cp.async.commit_group;")
#define CP_WAIT1()  asm volatile("cp.async.wait_group 1;")
#define CP_WAIT0()  asm volatile("cp.async.wait_group 0;")

#define MMA(C, A0, A1, A2, A3, B0, B1)                                         \
    asm volatile(                                                              \
        "mma.sync.aligned.m16n8k8.row.col.f32.tf32.tf32.f32 "                  \
        "{%0,%1,%2,%3},{%4,%5,%6,%7},{%8,%9},{%0,%1,%2,%3};"                   \
        : "+f"((C)[0]), "+f"((C)[1]), "+f"((C)[2]), "+f"((C)[3])               \
        : "r"(A0), "r"(A1), "r"(A2), "r"(A3), "r"(B0), "r"(B1))

#define MMAB(C, A0, A1, A2, A3, B0, B1)                                        \
    asm volatile(                                                              \
        "mma.sync.aligned.m16n8k16.row.col.f32.bf16.bf16.f32 "                 \
        "{%0,%1,%2,%3},{%4,%5,%6,%7},{%8,%9},{%0,%1,%2,%3};"                   \
        : "+f"((C)[0]), "+f"((C)[1]), "+f"((C)[2]), "+f"((C)[3])               \
        : "r"(A0), "r"(A1), "r"(A2), "r"(A3), "r"(B0), "r"(B1))

// ---------------- mega prepass ----------------
#define PRE_N0 (MR * KP)
#define PRE_N1 (DMODEL * KP)
#define PRE_TOT (PRE_N0 + 4 * PRE_N1)

__global__ __launch_bounds__(256) void prepass(const float* __restrict__ X,
                                               const float* __restrict__ Wv,
                                               const float* __restrict__ Wo,
                                               const float* __restrict__ Wq,
                                               const float* __restrict__ Wk) {
    int i = blockIdx.x * 256 + threadIdx.x;
    if (i < PRE_N0) {
        float2 v = ((const float2*)X)[i];
        unsigned hh, ll;
        bsplit(v.x, v.y, hh, ll);
        g_Xh[i] = hh;
        g_Xl[i] = ll;
        float2 o;
        o.x = __uint_as_float(f2t(v.x));
        o.y = __uint_as_float(f2t(v.y));
        ((float2*)g_Xr)[i] = o;
        return;
    }
    i -= PRE_N0;
    if (i < PRE_N1) {
        float2 v = ((const float2*)Wv)[i];
        unsigned hh, ll;
        bsplit(v.x, v.y, hh, ll);
        g_Wvh[i] = hh;
        g_Wvl[i] = ll;
        return;
    }
    i -= PRE_N1;
    if (i < PRE_N1) {
        float2 v = ((const float2*)Wo)[i];
        unsigned hh, ll;
        bsplit(v.x, v.y, hh, ll);
        g_Woh[i] = hh;
        g_Wol[i] = ll;
        return;
    }
    i -= PRE_N1;
    if (i < PRE_N1) {
        float2 v = ((const float2*)Wq)[i];
        float2 o;
        o.x = __uint_as_float(f2t(v.x));
        o.y = __uint_as_float(f2t(v.y));
        ((float2*)g_Wr)[i] = o;
        return;
    }
    i -= PRE_N1;
    if (i < PRE_N1) {
        float2 v = ((const float2*)Wk)[i];
        float2 o;
        o.x = __uint_as_float(f2t(v.x));
        o.y = __uint_as_float(f2t(v.y));
        ((float2*)(g_Wr + (size_t)DMODEL * DMODEL))[i] = o;
    }
}

// ---------------- qk tile body (BK=32, 2-stage, mixed split) ----------------
#define QK_SS   (128 * 36)

template <int SPLIT>
__device__ __forceinline__ void qk_body(const float* __restrict__ Asrc,
                                        const float* __restrict__ Bsrc,
                                        float* __restrict__ Y,
                                        int m0, int col0,
                                        float* __restrict__ Asm,
                                        float* __restrict__ Bsm) {
    const int tid = threadIdx.x, lane = tid & 31, warp = tid >> 5;
    const int g = lane >> 2, tg = lane & 3;
    const int wm = warp >> 2, wn = warp & 3;

    float c[4][4][4] = {};

#define QK_LOAD(stage, k0)                                                     \
    do {                                                                       \
        float* As_ = Asm + (stage) * QK_SS;                                    \
        float* Bs_ = Bsm + (stage) * QK_SS;                                    \
        _Pragma("unroll")                                                      \
        for (int t = 0; t < 4; t++) {                                          \
            int idx = tid + t * 256;                                           \
            int r = idx >> 3, c4 = (idx & 7) * 4;                              \
            cpa16(&As_[r * 36 + c4], &Asrc[(size_t)r * DMODEL + (k0) + c4]);   \
            cpa16(&Bs_[r * 36 + c4], &Bsrc[(size_t)r * DMODEL + (k0) + c4]);   \
        }                                                                      \
    } while (0)

    QK_LOAD(0, 0);
    CP_COMMIT();

    const int nIt = DMODEL / 32;
    for (int it = 0; it < nIt; it++) {
        const int st = it & 1;
        if (it + 1 < nIt) {
            QK_LOAD(st ^ 1, (it + 1) * 32);
            CP_COMMIT();
            CP_WAIT1();
        } else {
            CP_WAIT0();
        }
        __syncthreads();

        const float* As_ = Asm + st * QK_SS;
        const float* Bs_ = Bsm + st * QK_SS;
#pragma unroll
        for (int kc = 0; kc < 4; kc++) {
            unsigned bh[4][2], bl[4][2];
#pragma unroll
            for (int ni = 0; ni < 4; ni++) {
                int nb = (wn * 32 + ni * 8 + g) * 36 + kc * 8 + tg;
                float b0 = Bs_[nb];
                float b1 = Bs_[nb + 4];
                if (SPLIT == 3) {
                    bh[ni][0] = f2t(b0);
                    bh[ni][1] = f2t(b1);
                    bl[ni][0] = f2t(b0 - __uint_as_float(bh[ni][0]));
                    bl[ni][1] = f2t(b1 - __uint_as_float(bh[ni][1]));
                } else {
                    bh[ni][0] = __float_as_uint(b0);
                    bh[ni][1] = __float_as_uint(b1);
                }
            }
#pragma unroll
            for (int mi = 0; mi < 4; mi++) {
                int r1 = (wm * 64 + mi * 16 + g) * 36 + kc * 8 + tg;
                int r2 = r1 + 8 * 36;
                float a0 = As_[r1];
                float a1 = As_[r2];
                float a2 = As_[r1 + 4];
                float a3 = As_[r2 + 4];
                unsigned ah0, ah1, ah2, ah3;
                unsigned al0 = 0, al1 = 0, al2 = 0, al3 = 0;
                if (SPLIT == 3) {
                    ah0 = f2t(a0); ah1 = f2t(a1); ah2 = f2t(a2); ah3 = f2t(a3);
                    al0 = f2t(a0 - __uint_as_float(ah0));
                    al1 = f2t(a1 - __uint_as_float(ah1));
                    al2 = f2t(a2 - __uint_as_float(ah2));
                    al3 = f2t(a3 - __uint_as_float(ah3));
                } else {
                    ah0 = __float_as_uint(a0); ah1 = __float_as_uint(a1);
                    ah2 = __float_as_uint(a2); ah3 = __float_as_uint(a3);
                }
#pragma unroll
                for (int ni = 0; ni < 4; ni++) {
                    MMA(c[mi][ni], ah0, ah1, ah2, ah3, bh[ni][0], bh[ni][1]);
                    if (SPLIT == 3) {
                        MMA(c[mi][ni], ah0, ah1, ah2, ah3, bl[ni][0], bl[ni][1]);
                        MMA(c[mi][ni], al0, al1, al2, al3, bh[ni][0], bh[ni][1]);
                    }
                }
            }
        }
        __syncthreads();
    }
#undef QK_LOAD

#pragma unroll
    for (int mi = 0; mi < 4; mi++)
#pragma unroll
        for (int ni = 0; ni < 4; ni++) {
            int r = m0 + wm * 64 + mi * 16 + g;
            int col = col0 + wn * 32 + ni * 8 + 2 * tg;
            *(float2*)&Y[(size_t)r * DMODEL + col] = make_float2(c[mi][ni][0], c[mi][ni][1]);
            *(float2*)&Y[(size_t)(r + 8) * DMODEL + col] = make_float2(c[mi][ni][2], c[mi][ni][3]);
        }
}

// ---------------- bf16x3 tile body ----------------
__device__ __forceinline__ void bf3_body(const unsigned* __restrict__ Ah,
                                         const unsigned* __restrict__ Al,
                                         const unsigned* __restrict__ Bh,
                                         const unsigned* __restrict__ Bl,
                                         float* __restrict__ Y,
                                         int m0, int n0, int N, int Kp,
                                         unsigned* __restrict__ dsm) {
    const int AS = 128 * 20;
    const int tid = threadIdx.x, lane = tid & 31, warp = tid >> 5;
    const int g = lane >> 2, tg = lane & 3;
    const int wm = warp >> 2, wn = warp & 3;
    const int lr = tid >> 2, lc = (tid & 3) * 4;

    float c[4][4][4] = {};

    {
        unsigned* base = dsm;
#pragma unroll
        for (int t = 0; t < 2; t++) {
            int r = lr + t * 64;
            cpa16(&base[0 * AS + r * 20 + lc], &Ah[(size_t)(m0 + r) * Kp + lc]);
            cpa16(&base[1 * AS + r * 20 + lc], &Al[(size_t)(m0 + r) * Kp + lc]);
            cpa16(&base[2 * AS + r * 20 + lc], &Bh[(size_t)(n0 + r) * Kp + lc]);
            cpa16(&base[3 * AS + r * 20 + lc], &Bl[(size_t)(n0 + r) * Kp + lc]);
        }
        CP_COMMIT();
    }

    const int nIt = Kp / 16;
    for (int it = 0; it < nIt; it++) {
        const int st = it & 1;
        if (it + 1 < nIt) {
            const int k0 = (it + 1) * 16;
            unsigned* base = dsm + (st ^ 1) * 4 * AS;
#pragma unroll
            for (int t = 0; t < 2; t++) {
                int r = lr + t * 64;
                cpa16(&base[0 * AS + r * 20 + lc], &Ah[(size_t)(m0 + r) * Kp + k0 + lc]);
                cpa16(&base[1 * AS + r * 20 + lc], &Al[(size_t)(m0 + r) * Kp + k0 + lc]);
                cpa16(&base[2 * AS + r * 20 + lc], &Bh[(size_t)(n0 + r) * Kp + k0 + lc]);
                cpa16(&base[3 * AS + r * 20 + lc], &Bl[(size_t)(n0 + r) * Kp + k0 + lc]);
            }
            CP_COMMIT();
            CP_WAIT1();
        } else {
            CP_WAIT0();
        }
        __syncthreads();

        unsigned* sAh = dsm + st * 4 * AS;
        unsigned* sAl = sAh + AS;
        unsigned* sBh = sAh + 2 * AS;
        unsigned* sBl = sAh + 3 * AS;
#pragma unroll
        for (int kc = 0; kc < 2; kc++) {
            unsigned bhf[4][2], blf[4][2];
#pragma unroll
            for (int ni = 0; ni < 4; ni++) {
                int nb = (wn * 32 + ni * 8 + g) * 20 + kc * 8 + tg;
                bhf[ni][0] = sBh[nb];
                bhf[ni][1] = sBh[nb + 4];
                blf[ni][0] = sBl[nb];
                blf[ni][1] = sBl[nb + 4];
            }
#pragma unroll
            for (int mi = 0; mi < 4; mi++) {
                int r1 = (wm * 64 + mi * 16 + g) * 20 + kc * 8 + tg;
                int r2 = r1 + 8 * 20;
                unsigned ah0 = sAh[r1], ah1 = sAh[r2], ah2 = sAh[r1 + 4], ah3 = sAh[r2 + 4];
                unsigned al0 = sAl[r1], al1 = sAl[r2], al2 = sAl[r1 + 4], al3 = sAl[r2 + 4];
#pragma unroll
                for (int ni = 0; ni < 4; ni++) {
                    MMAB(c[mi][ni], ah0, ah1, ah2, ah3, bhf[ni][0], bhf[ni][1]);
                    MMAB(c[mi][ni], ah0, ah1, ah2, ah3, blf[ni][0], blf[ni][1]);
                    MMAB(c[mi][ni], al0, al1, al2, al3, bhf[ni][0], bhf[ni][1]);
                }
            }
        }
        __syncthreads();
    }

#pragma unroll
    for (int mi = 0; mi < 4; mi++)
#pragma unroll
        for (int ni = 0; ni < 4; ni++) {
            int r = m0 + wm * 64 + mi * 16 + g;
            int col = n0 + wn * 32 + ni * 8 + 2 * tg;
            *(float2*)&Y[(size_t)r * N + col] = make_float2(c[mi][ni][0], c[mi][ni][1]);
            *(float2*)&Y[(size_t)(r + 8) * N + col] = make_float2(c[mi][ni][2], c[mi][ni][3]);
        }
}

// ---------------- fused projections: QK (mixed tf32) + V (bf16x3) ----------
#define PROJ_SMEM (2 * 4 * 128 * 20 * 4)   // 81920 B

__global__ __launch_bounds__(256) void proj_fused(const float* __restrict__ X,
                                                  const float* __restrict__ Wq,
                                                  const float* __restrict__ Wk,
                                                  const float* __restrict__ Xr,
                                                  const float* __restrict__ Wr,
                                                  float* __restrict__ Q,
                                                  float* __restrict__ K,
                                                  float* __restrict__ V) {
    extern __shared__ float fsm[];
    const int xt = blockIdx.x;
    const int m0 = blockIdx.y * 128;

    if (xt < 16) {
        float* Asm = fsm;
        float* Bsm = fsm + 2 * QK_SS;
        float* Y = (xt < 8) ? Q : K;
        const int col0 = (xt & 7) * 128;
        if (xt == 0 || xt == 8) {
            const float* Asrc = X + (size_t)m0 * DMODEL;
            const float* Bsrc = (xt < 8) ? Wq : Wk;
            qk_body<3>(Asrc, Bsrc, Y, m0, col0, Asm, Bsm);
        } else {
            const float* Asrc = Xr + (size_t)m0 * DMODEL;
            const float* Bsrc = Wr + (size_t)xt * 128 * DMODEL;
            qk_body<1>(Asrc, Bsrc, Y, m0, col0, Asm, Bsm);
        }
    } else {
        bf3_body(g_Xh, g_Xl, g_Wvh, g_Wvl, V, m0, (xt - 16) * 128, DMODEL, KP,
                 (unsigned*)fsm);
    }
}

// ---------------- standalone bf16x3 GEMM (output projection) ----------
__global__ __launch_bounds__(256) void gemm_bf3(const unsigned* __restrict__ Ah,
                                                const unsigned* __restrict__ Al,
                                                const unsigned* __restrict__ Bh,
                                                const unsigned* __restrict__ Bl,
                                                float* __restrict__ Y,
                                                int M, int N, int Kp) {
    extern __shared__ unsigned dsm[];
    bf3_body(Ah, Al, Bh, Bl, Y, blockIdx.y * 128, blockIdx.x * 128, N, Kp, dsm);
}

// ---------------- row LayerNorm + scaled tf32 copy (R12 version) ----------------
__global__ __launch_bounds__(256) void ln_rows_t(float* __restrict__ Y,
                                                 const float* __restrict__ g,
                                                 const float* __restrict__ b,
                                                 unsigned* __restrict__ T,
                                                 float scale) {
    const int row = blockIdx.x;
    float* y = Y + (size_t)row * DMODEL;
    unsigned* t = T + (size_t)row * DMODEL;
    __shared__ float red[256];

    float s = 0.f;
    for (int i = threadIdx.x; i < DMODEL; i += 256) s += y[i];
    red[threadIdx.x] = s;
    __syncthreads();
    for (int o = 128; o > 0; o >>= 1) {
        if (threadIdx.x < o) red[threadIdx.x] += red[threadIdx.x + o];
        __syncthreads();
    }
    const float mu = red[0] * (1.0f / DMODEL);
    __syncthreads();

    float v = 0.f;
    for (int i = threadIdx.x; i < DMODEL; i += 256) {
        float d = y[i] - mu;
        v += d * d;
    }
    red[threadIdx.x] = v;
    __syncthreads();
    for (int o = 128; o > 0; o >>= 1) {
        if (threadIdx.x < o) red[threadIdx.x] += red[threadIdx.x + o];
        __syncthreads();
    }
    const float rstd = rsqrtf(red[0] * (1.0f / DMODEL) + 1e-5f);
    __syncthreads();

    for (int i = threadIdx.x; i < DMODEL; i += 256) {
        float val = (y[i] - mu) * rstd * g[i] + b[i];
        y[i] = val;
        t[i] = f2t(val * scale);
    }
}

// ---------------- V transpose + bf16 split (R12 version) ----------------
__global__ __launch_bounds__(256) void vt_split() {
    __shared__ float tile[64][68];
    const int b = blockIdx.z, h = blockIdx.y, n0 = blockIdx.x * 64;
    const int tid = threadIdx.x;
#pragma unroll
    for (int t = 0; t < 4; t++) {
        int idx = tid + t * 256;
        int r = idx >> 4, c4 = (idx & 15) * 4;
        *(float4*)&tile[r][c4] =
            *(const float4*)&g_V[(size_t)(b * SEQL + n0 + r) * DMODEL + h * DHEAD + c4];
    }
    __syncthreads();
#pragma unroll
    for (int t = 0; t < 8; t++) {
        int idx = tid + t * 256;
        int d = idx >> 5, j = idx & 31;
        unsigned hh, ll;
        bsplit(tile[2 * j][d], tile[2 * j + 1][d], hh, ll);
        size_t off = ((size_t)((b * NHEADS + h) * DHEAD + d)) * (SEQL / 2) + (n0 >> 1) + j;
        g_Vth[off] = hh;
        g_Vtl[off] = ll;
    }
}

// ---------------- head-0 scores + fused segment column-sums ----------------
// Upper tiles: C is structurally zero -> write ONLY the g_P zeros, skip F stores.
// (final_scan predicates its C loads with row>m, and overwrites every F cell.)
__global__ __launch_bounds__(256) void head0_tc() {
    const int tid = threadIdx.x, lane = tid & 31, warp = tid >> 5;
    const int g = lane >> 2, tg = lane & 3;
    const int wm = warp >> 2, wn = warp & 3;
    const int bb = blockIdx.z;
    const int r0 = blockIdx.y * 128, mm0 = blockIdx.x * 128;
    const size_t pbase = (size_t)(bb * NSEG + blockIdx.y) * SEQL + mm0;

    if (mm0 >= r0 + 128) {
        if (tid < 128) g_P[pbase + tid] = 0.f;
        return;
    }

    __shared__ float As[128][36];
    __shared__ float Bs[128][36];
    __shared__ float cs[128];
    const float* Aq = g_Q + (size_t)(bb * SEQL + r0) * DMODEL;
    const float* Bk = g_K + (size_t)(bb * SEQL + mm0) * DMODEL;
    const int lrow = tid >> 3, lcol = (tid & 7) * 4;

    float c[4][4][4] = {};

    for (int k0 = 0; k0 < 64; k0 += 32) {
#pragma unroll
        for (int it = 0; it < 4; it++) {
            int r = lrow + it * 32;
            *(float4*)&As[r][lcol] = *(const float4*)&Aq[(size_t)r * DMODEL + k0 + lcol];
            *(float4*)&Bs[r][lcol] = *(const float4*)&Bk[(size_t)r * DMODEL + k0 + lcol];
        }
        __syncthreads();
#pragma unroll
        for (int kc = 0; kc < 4; kc++) {
            unsigned bh[4][2], bl[4][2];
#pragma unroll
            for (int ni = 0; ni < 4; ni++) {
                int nb = wn * 32 + ni * 8;
                float b0 = Bs[nb + g][kc * 8 + tg];
                float b1 = Bs[nb + g][kc * 8 + tg + 4];
                bh[ni][0] = f2t(b0);
                bh[ni][1] = f2t(b1);
                bl[ni][0] = f2t(b0 - __uint_as_float(bh[ni][0]));
                bl[ni][1] = f2t(b1 - __uint_as_float(bh[ni][1]));
            }
#pragma unroll
            for (int mi = 0; mi < 4; mi++) {
                int rm = wm * 64 + mi * 16;
                float a0 = As[rm + g][kc * 8 + tg];
                float a1 = As[rm + g + 8][kc * 8 + tg];
                float a2 = As[rm + g][kc * 8 + tg + 4];
                float a3 = As[rm + g + 8][kc * 8 + tg + 4];
                unsigned ah0 = f2t(a0), ah1 = f2t(a1), ah2 = f2t(a2), ah3 = f2t(a3);
                unsigned al0 = f2t(a0 - __uint_as_float(ah0));
                unsigned al1 = f2t(a1 - __uint_as_float(ah1));
                unsigned al2 = f2t(a2 - __uint_as_float(ah2));
                unsigned al3 = f2t(a3 - __uint_as_float(ah3));
#pragma unroll
                for (int ni = 0; ni < 4; ni++) {
                    MMA(c[mi][ni], ah0, ah1, ah2, ah3, bh[ni][0], bh[ni][1]);
                    MMA(c[mi][ni], ah0, ah1, ah2, ah3, bl[ni][0], bl[ni][1]);
                    MMA(c[mi][ni], al0, al1, al2, al3, bh[ni][0], bh[ni][1]);
                }
            }
        }
        __syncthreads();
    }

    if (tid < 128) cs[tid] = 0.f;
    __syncthreads();

    float csl[4][2] = {};
#pragma unroll
    for (int mi = 0; mi < 4; mi++)
#pragma unroll
        for (int ni = 0; ni < 4; ni++) {
            int r1 = r0 + wm * 64 + mi * 16 + g;
            int r2 = r1 + 8;
            int m = mm0 + wn * 32 + ni * 8 + 2 * tg;
            float v0 = c[mi][ni][0] * 0.125f;
            float v1 = c[mi][ni][1] * 0.125f;
            float v2 = c[mi][ni][2] * 0.125f;
            float v3 = c[mi][ni][3] * 0.125f;
            v0 = (m >= 1 && m < r1) ? fmaxf(v0, 0.f) : 0.f;
            v1 = (m + 1 < r1) ? fmaxf(v1, 0.f) : 0.f;
            v2 = (m >= 1 && m < r2) ? fmaxf(v2, 0.f) : 0.f;
            v3 = (m + 1 < r2) ? fmaxf(v3, 0.f) : 0.f;
            *(float2*)&g_F[(size_t)(bb * SEQL + r1) * SEQL + m] = make_float2(v0, v1);
            *(float2*)&g_F[(size_t)(bb * SEQL + r2) * SEQL + m] = make_float2(v2, v3);
            csl[ni][0] += v0 + v2;
            csl[ni][1] += v1 + v3;
        }

#pragma unroll
    for (int ni = 0; ni < 4; ni++)
#pragma unroll
        for (int j = 0; j < 2; j++) {
            float v = csl[ni][j];
            v += __shfl_xor_sync(0xffffffffu, v, 4);
            v += __shfl_xor_sync(0xffffffffu, v, 8);
            v += __shfl_xor_sync(0xffffffffu, v, 16);
            csl[ni][j] = v;
        }
    if (g == 0) {
#pragma unroll
        for (int ni = 0; ni < 4; ni++) {
            atomicAdd(&cs[wn * 32 + ni * 8 + 2 * tg], csl[ni][0]);
            atomicAdd(&cs[wn * 32 + ni * 8 + 2 * tg + 1], csl[ni][1]);
        }
    }
    __syncthreads();
    if (tid < 128) g_P[pbase + tid] = cs[tid];
}

// ---------------- single scan pass: segment prefix from raw g_P + in-place F -------
__global__ __launch_bounds__(256) void final_scan() {
    const int m = blockIdx.x * 256 + threadIdx.x;
    const int seg = blockIdx.y, b = blockIdx.z;
    float acc = 0.f;
    for (int s = 0; s < seg; s++)                    // prefix over earlier segments
        acc += g_P[(size_t)(b * NSEG + s) * SEQL + m];
    float* base = g_F + (size_t)(b * SEQL + seg * SEGROWS) * SEQL + m;
    const int r0 = seg * SEGROWS;
#pragma unroll 4
    for (int r = 0; r < SEGROWS; r++) {
        float c = (r0 + r > m) ? base[(size_t)r * SEQL] : 0.f;   // C==0 above diag
        base[(size_t)r * SEQL] = acc;
        acc += c;
    }
}

// ---------------- flash attention: BM=64, 128 threads, cp.async K/V ----------
#define ATTN_KSZ  (64 * 68)
#define ATTN_VSZ  (64 * 36)
#define ATTN_VHOFF (2 * ATTN_KSZ)
#define ATTN_VLOFF (2 * ATTN_KSZ + 2 * ATTN_VSZ)
#define ATTN_SMEM  ((2 * ATTN_KSZ + 4 * ATTN_VSZ) * 4)

__global__ __launch_bounds__(128) void attn_bf() {
    extern __shared__ unsigned sm[];
    const int b = blockIdx.z, h = blockIdx.y;
    const int qt = (int)gridDim.x - 1 - (int)blockIdx.x;
    const int q0 = qt * 64;
    const int tid = threadIdx.x, lane = tid & 31, w = tid >> 5;
    const int g = lane >> 2, tg = lane & 3;

    unsigned qa[8][4];
    const size_t qr1 = (size_t)(b * SEQL + q0 + w * 16 + g) * DMODEL + h * DHEAD;
    const size_t qr2 = qr1 + 8 * DMODEL;
#pragma unroll
    for (int kc = 0; kc < 8; kc++) {
        qa[kc][0] = g_Qt[qr1 + kc * 8 + tg];
        qa[kc][1] = g_Qt[qr2 + kc * 8 + tg];
        qa[kc][2] = g_Qt[qr1 + kc * 8 + tg + 4];
        qa[kc][3] = g_Qt[qr2 + kc * 8 + tg + 4];
    }

    float o[8][4] = {};
    float qm0 = -1e30f, qm1 = -1e30f, lsum0 = 0.f, lsum1 = 0.f;

    {
        const size_t kbase = (size_t)(b * SEQL) * DMODEL + h * DHEAD;
        const size_t vbase = (size_t)((b * NHEADS + h) * DHEAD) * (SEQL / 2);
#pragma unroll
        for (int t = 0; t < 8; t++) {
            int idx = tid + t * 128;
            int r = idx >> 4, c4 = (idx & 15) * 4;
            cpa16(&sm[r * 68 + c4], &g_Kt[kbase + (size_t)r * DMODEL + c4]);
        }
#pragma unroll
        for (int t = 0; t < 4; t++) {
            int idx = tid + t * 128;
            int r = idx >> 3, c4 = (idx & 7) * 4;
            cpa16(&sm[ATTN_VHOFF + r * 36 + c4], &g_Vth[vbase + (size_t)r * (SEQL / 2) + c4]);
            cpa16(&sm[ATTN_VLOFF + r * 36 + c4], &g_Vtl[vbase + (size_t)r * (SEQL / 2) + c4]);
        }
        CP_COMMIT();
    }

    for (int kt = 0; kt <= qt; kt++) {
        const int buf = kt & 1;
        const int m0 = kt * 64;
        if (kt < qt) {
            const int m0n = m0 + 64;
            const int nb = buf ^ 1;
            const size_t kbase = (size_t)(b * SEQL + m0n) * DMODEL + h * DHEAD;
            const size_t vbase = (size_t)((b * NHEADS + h) * DHEAD) * (SEQL / 2) + (m0n >> 1);
#pragma unroll
            for (int t = 0; t < 8; t++) {
                int idx = tid + t * 128;
                int r = idx >> 4, c4 = (idx & 15) * 4;
                cpa16(&sm[nb * ATTN_KSZ + r * 68 + c4], &g_Kt[kbase + (size_t)r * DMODEL + c4]);
            }
#pragma unroll
            for (int t = 0; t < 4; t++) {
                int idx = tid + t * 128;
                int r = idx >> 3, c4 = (idx & 7) * 4;
                cpa16(&sm[ATTN_VHOFF + nb * ATTN_VSZ + r * 36 + c4],
                      &g_Vth[vbase + (size_t)r * (SEQL / 2) + c4]);
                cpa16(&sm[ATTN_VLOFF + nb * ATTN_VSZ + r * 36 + c4],
                      &g_Vtl[vbase + (size_t)r * (SEQL / 2) + c4]);
            }
            CP_COMMIT();
            CP_WAIT1();
        } else {
            CP_WAIT0();
        }
        __syncthreads();

        const unsigned* sKt = sm + buf * ATTN_KSZ;
        const unsigned* sVh = sm + ATTN_VHOFF + buf * ATTN_VSZ;
        const unsigned* sVl = sm + ATTN_VLOFF + buf * ATTN_VSZ;

        float sc[8][4] = {};
#pragma unroll
        for (int kc = 0; kc < 8; kc++) {
#pragma unroll
            for (int ni = 0; ni < 8; ni++) {
                unsigned b0 = sKt[(ni * 8 + g) * 68 + kc * 8 + tg];
                unsigned b1 = sKt[(ni * 8 + g) * 68 + kc * 8 + tg + 4];
                MMA(sc[ni], qa[kc][0], qa[kc][1], qa[kc][2], qa[kc][3], b0, b1);
            }
        }

        const bool diag = (kt == qt);
        const int lr1 = w * 16 + g, lr2 = lr1 + 8;
        const size_t frow1 = (size_t)(b * SEQL + q0 + lr1) * SEQL + m0;
        const size_t frow2 = (size_t)(b * SEQL + q0 + lr2) * SEQL + m0;
        float mx0 = -1e30f, mx1 = -1e30f;
#pragma unroll
        for (int ni = 0; ni < 8; ni++) {
            int cl = ni * 8 + 2 * tg;
            float2 f1 = *(const float2*)&g_F[frow1 + cl];
            float2 f2 = *(const float2*)&g_F[frow2 + cl];
            float v0 = sc[ni][0] - f1.x;
            float v1 = sc[ni][1] - f1.y;
            float v2 = sc[ni][2] - f2.x;
            float v3 = sc[ni][3] - f2.y;
            if (diag) {
                if (cl > lr1) v0 = -1e30f;
                if (cl + 1 > lr1) v1 = -1e30f;
                if (cl > lr2) v2 = -1e30f;
                if (cl + 1 > lr2) v3 = -1e30f;
            }
            sc[ni][0] = v0; sc[ni][1] = v1; sc[ni][2] = v2; sc[ni][3] = v3;
            mx0 = fmaxf(mx0, fmaxf(v0, v1));
            mx1 = fmaxf(mx1, fmaxf(v2, v3));
        }
        mx0 = fmaxf(mx0, __shfl_xor_sync(0xffffffffu, mx0, 1));
        mx0 = fmaxf(mx0, __shfl_xor_sync(0xffffffffu, mx0, 2));
        mx1 = fmaxf(mx1, __shfl_xor_sync(0xffffffffu, mx1, 1));
        mx1 = fmaxf(mx1, __shfl_xor_sync(0xffffffffu, mx1, 2));
        const float nm0 = fmaxf(qm0, mx0), nm1 = fmaxf(qm1, mx1);
        const float s0 = __expf(qm0 - nm0), s1 = __expf(qm1 - nm1);
        float ps0 = 0.f, ps1 = 0.f;
#pragma unroll
        for (int ni = 0; ni < 8; ni++) {
            float e0 = __expf(sc[ni][0] - nm0);
            float e1 = __expf(sc[ni][1] - nm0);
            float e2 = __expf(sc[ni][2] - nm1);
            float e3 = __expf(sc[ni][3] - nm1);
            sc[ni][0] = e0; sc[ni][1] = e1; sc[ni][2] = e2; sc[ni][3] = e3;
            ps0 += e0 + e1;
            ps1 += e2 + e3;
            o[ni][0] *= s0; o[ni][1] *= s0; o[ni][2] *= s1; o[ni][3] *= s1;
        }
        ps0 += __shfl_xor_sync(0xffffffffu, ps0, 1);
        ps0 += __shfl_xor_sync(0xffffffffu, ps0, 2);
        ps1 += __shfl_xor_sync(0xffffffffu, ps1, 1);
        ps1 += __shfl_xor_sync(0xffffffffu, ps1, 2);
        lsum0 = lsum0 * s0 + ps0;
        lsum1 = lsum1 * s1 + ps1;
        qm0 = nm0; qm1 = nm1;

#pragma unroll
        for (int kc2 = 0; kc2 < 4; kc2++) {
            unsigned ph0, pl0, ph1, pl1, ph2, pl2, ph3, pl3;
            bsplit(sc[kc2 * 2][0], sc[kc2 * 2][1], ph0, pl0);
            bsplit(sc[kc2 * 2][2], sc[kc2 * 2][3], ph1, pl1);
            bsplit(sc[kc2 * 2 + 1][0], sc[kc2 * 2 + 1][1], ph2, pl2);
            bsplit(sc[kc2 * 2 + 1][2], sc[kc2 * 2 + 1][3], ph3, pl3);
#pragma unroll
            for (int ni = 0; ni < 8; ni++) {
                int vb = (ni * 8 + g) * 36 + kc2 * 8 + tg;
                unsigned vh0 = sVh[vb], vh1 = sVh[vb + 4];
                unsigned vl0 = sVl[vb], vl1 = sVl[vb + 4];
                MMAB(o[ni], ph0, ph1, ph2, ph3, vh0, vh1);
                MMAB(o[ni], ph0, ph1, ph2, ph3, vl0, vl1);
                MMAB(o[ni], pl0, pl1, pl2, pl3, vh0, vh1);
            }
        }
        __syncthreads();
    }

    const float i0 = 1.0f / lsum0, i1 = 1.0f / lsum1;
    const size_t or1 = (size_t)(b * SEQL + q0 + w * 16 + g) * KP + h * 32;
    const size_t or2 = or1 + 8 * KP;
#pragma unroll
    for (int ni = 0; ni < 8; ni++) {
        unsigned hh, ll;
        bsplit(o[ni][0] * i0, o[ni][1] * i0, hh, ll);
        g_Oh[or1 + ni * 4 + tg] = hh;
        g_Ol[or1 + ni * 4 + tg] = ll;
        bsplit(o[ni][2] * i1, o[ni][3] * i1, hh, ll);
        g_Oh[or2 + ni * 4 + tg] = hh;
        g_Ol[or2 + ni * 4 + tg] = ll;
    }
}

// ---------------- launch ----------------
extern "C" void kernel_launch(void* const* d_in, const int* in_sizes, int n_in,
                              void* d_out, int out_size) {
    const float* X  = (const float*)d_in[0];
    const float* Wq = (const float*)d_in[1];
    const float* Wk = (const float*)d_in[2];
    const float* Wv = (const float*)d_in[3];
    const float* Wo = (const float*)d_in[4];
    const float* gq = (const float*)d_in[5];
    const float* bq = (const float*)d_in[6];
    const float* gk = (const float*)d_in[7];
    const float* bk = (const float*)d_in[8];
    float* out = (float*)d_out;

    float *pQ, *pK, *pV, *pXr, *pWr;
    unsigned *pQt, *pKt, *pWoh, *pWol, *pOh, *pOl;
    cudaGetSymbolAddress((void**)&pQ, g_Q);
    cudaGetSymbolAddress((void**)&pK, g_K);
    cudaGetSymbolAddress((void**)&pV, g_V);
    cudaGetSymbolAddress((void**)&pXr, g_Xr);
    cudaGetSymbolAddress((void**)&pWr, g_Wr);
    cudaGetSymbolAddress((void**)&pQt, g_Qt);
    cudaGetSymbolAddress((void**)&pKt, g_Kt);
    cudaGetSymbolAddress((void**)&pWoh, g_Woh);
    cudaGetSymbolAddress((void**)&pWol, g_Wol);
    cudaGetSymbolAddress((void**)&pOh, g_Oh);
    cudaGetSymbolAddress((void**)&pOl, g_Ol);

    cudaFuncSetAttribute(proj_fused, cudaFuncAttributeMaxDynamicSharedMemorySize, PROJ_SMEM);
    cudaFuncSetAttribute(gemm_bf3, cudaFuncAttributeMaxDynamicSharedMemorySize, PROJ_SMEM);
    cudaFuncSetAttribute(attn_bf, cudaFuncAttributeMaxDynamicSharedMemorySize, ATTN_SMEM);

    prepass<<<(PRE_TOT + 255) / 256, 256>>>(X, Wv, Wo, Wq, Wk);

    proj_fused<<<dim3(24, MR / 128), 256, PROJ_SMEM>>>(X, Wq, Wk, pXr, pWr, pQ, pK, pV);

    ln_rows_t<<<MR, 256>>>(pQ, gq, bq, pQt, 0.125f);
    ln_rows_t<<<MR, 256>>>(pK, gk, bk, pKt, 1.0f);
    vt_split<<<dim3(SEQL / 64, NHEADS, BATCH), 256>>>();

    head0_tc<<<dim3(SEQL / 128, SEQL / 128, BATCH), 256>>>();
    final_scan<<<dim3(SEQL / 256, NSEG, BATCH), 256>>>();

    attn_bf<<<dim3(SEQL / 64, NHEADS, BATCH), 128, ATTN_SMEM>>>();

    gemm_bf3<<<dim3(DMODEL / 128, MR / 128), 256, PROJ_SMEM>>>(pOh, pOl, pWoh, pWol, out,
                                                               MR, DMODEL, KP);
}

// round 15
// speedup vs baseline: 1.0182x; 1.0091x over previous
#include <cuda_runtime.h>
#include <cuda_bf16.h>
#include <math.h>

#define SEQL   2048
#define BATCH  2
#define DMODEL 1024
#define NHEADS 16
#define DHEAD  64
#define MR     (BATCH * SEQL)   // 4096 rows
#define NSEG   16
#define SEGROWS (SEQL / NSEG)   // 128
#define KP     (DMODEL / 2)     // 512 bf16-pair columns

// ---------------- scratch ----------------
__device__ float    g_Q[(size_t)MR * DMODEL];
__device__ float    g_K[(size_t)MR * DMODEL];
__device__ float    g_V[(size_t)MR * DMODEL];
__device__ float    g_Xr[(size_t)MR * DMODEL];         // tf32-rounded X (x1 path)
__device__ float    g_Wr[(size_t)2 * DMODEL * DMODEL]; // Wq then Wk, rounded
__device__ unsigned g_Qt[(size_t)MR * DMODEL];         // tf32 hi bits, PRE-SCALED by 0.125
__device__ unsigned g_Kt[(size_t)MR * DMODEL];
__device__ unsigned g_Xh[(size_t)MR * KP];
__device__ unsigned g_Xl[(size_t)MR * KP];
__device__ unsigned g_Wvh[(size_t)DMODEL * KP];
__device__ unsigned g_Wvl[(size_t)DMODEL * KP];
__device__ unsigned g_Woh[(size_t)DMODEL * KP];
__device__ unsigned g_Wol[(size_t)DMODEL * KP];
__device__ unsigned g_Vth[(size_t)BATCH * NHEADS * DHEAD * (SEQL / 2)];
__device__ unsigned g_Vtl[(size_t)BATCH * NHEADS * DHEAD * (SEQL / 2)];
__device__ unsigned g_Oh[(size_t)MR * KP];
__device__ unsigned g_Ol[(size_t)MR * KP];
__device__ float    g_F[(size_t)BATCH * SEQL * SEQL];
__device__ float    g_P[(size_t)BATCH * NSEG * SEQL];

// ---------------- helpers ----------------
__device__ __forceinline__ unsigned f2t(float x) {
    unsigned r;
    asm("cvt.rna.tf32.f32 %0, %1;" : "=r"(r) : "f"(x));
    return r;
}

__device__ __forceinline__ void bsplit(float x0, float x1, unsigned& h, unsigned& l) {
    asm("cvt.rn.bf16x2.f32 %0, %1, %2;" : "=r"(h) : "f"(x1), "f"(x0));
    __nv_bfloat162 hb = *reinterpret_cast<__nv_bfloat162*>(&h);
    float2 hf = __bfloat1622float2(hb);
    float r0 = x0 - hf.x, r1 = x1 - hf.y;
    asm("cvt.rn.bf16x2.f32 %0, %1, %2;" : "=r"(l) : "f"(r1), "f"(r0));
}

__device__ __forceinline__ void cpa16(void* smem, const void* gmem) {
    unsigned s = (unsigned)__cvta_generic_to_shared(smem);
    asm volatile("cp.async.cg.shared.global [%0], [%1], 16;" :: "r"(s), "l"(gmem));
}
#define CP_COMMIT() asm volatile("cp.async.commit_group;")
#define CP_WAIT1()  asm volatile("cp.async.wait_group 1;")
#define CP_WAIT0()  asm volatile("cp.async.wait_group 0;")

#define MMA(C, A0, A1, A2, A3, B0, B1)                                         \
    asm volatile(                                                              \
        "mma.sync.aligned.m16n8k8.row.col.f32.tf32.tf32.f32 "                  \
        "{%0,%1,%2,%3},{%4,%5,%6,%7},{%8,%9},{%0,%1,%2,%3};"                   \
        : "+f"((C)[0]), "+f"((C)[1]), "+f"((C)[2]), "+f"((C)[3])               \
        : "r"(A0), "r"(A1), "r"(A2), "r"(A3), "r"(B0), "r"(B1))

#define MMAB(C, A0, A1, A2, A3, B0, B1)                                        \
    asm volatile(                                                              \
        "mma.sync.aligned.m16n8k16.row.col.f32.bf16.bf16.f32 "                 \
        "{%0,%1,%2,%3},{%4,%5,%6,%7},{%8,%9},{%0,%1,%2,%3};"                   \
        : "+f"((C)[0]), "+f"((C)[1]), "+f"((C)[2]), "+f"((C)[3])               \
        : "r"(A0), "r"(A1), "r"(A2), "r"(A3), "r"(B0), "r"(B1))

// ---------------- mega prepass ----------------
#define PRE_N0 (MR * KP)
#define PRE_N1 (DMODEL * KP)
#define PRE_TOT (PRE_N0 + 4 * PRE_N1)

__global__ __launch_bounds__(256) void prepass(const float* __restrict__ X,
                                               const float* __restrict__ Wv,
                                               const float* __restrict__ Wo,
                                               const float* __restrict__ Wq,
                                               const float* __restrict__ Wk) {
    int i = blockIdx.x * 256 + threadIdx.x;
    if (i < PRE_N0) {
        float2 v = ((const float2*)X)[i];
        unsigned hh, ll;
        bsplit(v.x, v.y, hh, ll);
        g_Xh[i] = hh;
        g_Xl[i] = ll;
        float2 o;
        o.x = __uint_as_float(f2t(v.x));
        o.y = __uint_as_float(f2t(v.y));
        ((float2*)g_Xr)[i] = o;
        return;
    }
    i -= PRE_N0;
    if (i < PRE_N1) {
        float2 v = ((const float2*)Wv)[i];
        unsigned hh, ll;
        bsplit(v.x, v.y, hh, ll);
        g_Wvh[i] = hh;
        g_Wvl[i] = ll;
        return;
    }
    i -= PRE_N1;
    if (i < PRE_N1) {
        float2 v = ((const float2*)Wo)[i];
        unsigned hh, ll;
        bsplit(v.x, v.y, hh, ll);
        g_Woh[i] = hh;
        g_Wol[i] = ll;
        return;
    }
    i -= PRE_N1;
    if (i < PRE_N1) {
        float2 v = ((const float2*)Wq)[i];
        float2 o;
        o.x = __uint_as_float(f2t(v.x));
        o.y = __uint_as_float(f2t(v.y));
        ((float2*)g_Wr)[i] = o;
        return;
    }
    i -= PRE_N1;
    if (i < PRE_N1) {
        float2 v = ((const float2*)Wk)[i];
        float2 o;
        o.x = __uint_as_float(f2t(v.x));
        o.y = __uint_as_float(f2t(v.y));
        ((float2*)(g_Wr + (size_t)DMODEL * DMODEL))[i] = o;
    }
}

// ---------------- qk tile body (BK=32, 2-stage, mixed split) ----------------
#define QK_SS   (128 * 36)

template <int SPLIT>
__device__ __forceinline__ void qk_body(const float* __restrict__ Asrc,
                                        const float* __restrict__ Bsrc,
                                        float* __restrict__ Y,
                                        int m0, int col0,
                                        float* __restrict__ Asm,
                                        float* __restrict__ Bsm) {
    const int tid = threadIdx.x, lane = tid & 31, warp = tid >> 5;
    const int g = lane >> 2, tg = lane & 3;
    const int wm = warp >> 2, wn = warp & 3;

    float c[4][4][4] = {};

#define QK_LOAD(stage, k0)                                                     \
    do {                                                                       \
        float* As_ = Asm + (stage) * QK_SS;                                    \
        float* Bs_ = Bsm + (stage) * QK_SS;                                    \
        _Pragma("unroll")                                                      \
        for (int t = 0; t < 4; t++) {                                          \
            int idx = tid + t * 256;                                           \
            int r = idx >> 3, c4 = (idx & 7) * 4;                              \
            cpa16(&As_[r * 36 + c4], &Asrc[(size_t)r * DMODEL + (k0) + c4]);   \
            cpa16(&Bs_[r * 36 + c4], &Bsrc[(size_t)r * DMODEL + (k0) + c4]);   \
        }                                                                      \
    } while (0)

    QK_LOAD(0, 0);
    CP_COMMIT();

    const int nIt = DMODEL / 32;
    for (int it = 0; it < nIt; it++) {
        const int st = it & 1;
        if (it + 1 < nIt) {
            QK_LOAD(st ^ 1, (it + 1) * 32);
            CP_COMMIT();
            CP_WAIT1();
        } else {
            CP_WAIT0();
        }
        __syncthreads();

        const float* As_ = Asm + st * QK_SS;
        const float* Bs_ = Bsm + st * QK_SS;
#pragma unroll
        for (int kc = 0; kc < 4; kc++) {
            unsigned bh[4][2], bl[4][2];
#pragma unroll
            for (int ni = 0; ni < 4; ni++) {
                int nb = (wn * 32 + ni * 8 + g) * 36 + kc * 8 + tg;
                float b0 = Bs_[nb];
                float b1 = Bs_[nb + 4];
                if (SPLIT == 3) {
                    bh[ni][0] = f2t(b0);
                    bh[ni][1] = f2t(b1);
                    bl[ni][0] = f2t(b0 - __uint_as_float(bh[ni][0]));
                    bl[ni][1] = f2t(b1 - __uint_as_float(bh[ni][1]));
                } else {
                    bh[ni][0] = __float_as_uint(b0);
                    bh[ni][1] = __float_as_uint(b1);
                }
            }
#pragma unroll
            for (int mi = 0; mi < 4; mi++) {
                int r1 = (wm * 64 + mi * 16 + g) * 36 + kc * 8 + tg;
                int r2 = r1 + 8 * 36;
                float a0 = As_[r1];
                float a1 = As_[r2];
                float a2 = As_[r1 + 4];
                float a3 = As_[r2 + 4];
                unsigned ah0, ah1, ah2, ah3;
                unsigned al0 = 0, al1 = 0, al2 = 0, al3 = 0;
                if (SPLIT == 3) {
                    ah0 = f2t(a0); ah1 = f2t(a1); ah2 = f2t(a2); ah3 = f2t(a3);
                    al0 = f2t(a0 - __uint_as_float(ah0));
                    al1 = f2t(a1 - __uint_as_float(ah1));
                    al2 = f2t(a2 - __uint_as_float(ah2));
                    al3 = f2t(a3 - __uint_as_float(ah3));
                } else {
                    ah0 = __float_as_uint(a0); ah1 = __float_as_uint(a1);
                    ah2 = __float_as_uint(a2); ah3 = __float_as_uint(a3);
                }
#pragma unroll
                for (int ni = 0; ni < 4; ni++) {
                    MMA(c[mi][ni], ah0, ah1, ah2, ah3, bh[ni][0], bh[ni][1]);
                    if (SPLIT == 3) {
                        MMA(c[mi][ni], ah0, ah1, ah2, ah3, bl[ni][0], bl[ni][1]);
                        MMA(c[mi][ni], al0, al1, al2, al3, bh[ni][0], bh[ni][1]);
                    }
                }
            }
        }
        __syncthreads();
    }
#undef QK_LOAD

#pragma unroll
    for (int mi = 0; mi < 4; mi++)
#pragma unroll
        for (int ni = 0; ni < 4; ni++) {
            int r = m0 + wm * 64 + mi * 16 + g;
            int col = col0 + wn * 32 + ni * 8 + 2 * tg;
            *(float2*)&Y[(size_t)r * DMODEL + col] = make_float2(c[mi][ni][0], c[mi][ni][1]);
            *(float2*)&Y[(size_t)(r + 8) * DMODEL + col] = make_float2(c[mi][ni][2], c[mi][ni][3]);
        }
}

// ---------------- bf16x3 tile body ----------------
__device__ __forceinline__ void bf3_body(const unsigned* __restrict__ Ah,
                                         const unsigned* __restrict__ Al,
                                         const unsigned* __restrict__ Bh,
                                         const unsigned* __restrict__ Bl,
                                         float* __restrict__ Y,
                                         int m0, int n0, int N, int Kp,
                                         unsigned* __restrict__ dsm) {
    const int AS = 128 * 20;
    const int tid = threadIdx.x, lane = tid & 31, warp = tid >> 5;
    const int g = lane >> 2, tg = lane & 3;
    const int wm = warp >> 2, wn = warp & 3;
    const int lr = tid >> 2, lc = (tid & 3) * 4;

    float c[4][4][4] = {};

    {
        unsigned* base = dsm;
#pragma unroll
        for (int t = 0; t < 2; t++) {
            int r = lr + t * 64;
            cpa16(&base[0 * AS + r * 20 + lc], &Ah[(size_t)(m0 + r) * Kp + lc]);
            cpa16(&base[1 * AS + r * 20 + lc], &Al[(size_t)(m0 + r) * Kp + lc]);
            cpa16(&base[2 * AS + r * 20 + lc], &Bh[(size_t)(n0 + r) * Kp + lc]);
            cpa16(&base[3 * AS + r * 20 + lc], &Bl[(size_t)(n0 + r) * Kp + lc]);
        }
        CP_COMMIT();
    }

    const int nIt = Kp / 16;
    for (int it = 0; it < nIt; it++) {
        const int st = it & 1;
        if (it + 1 < nIt) {
            const int k0 = (it + 1) * 16;
            unsigned* base = dsm + (st ^ 1) * 4 * AS;
#pragma unroll
            for (int t = 0; t < 2; t++) {
                int r = lr + t * 64;
                cpa16(&base[0 * AS + r * 20 + lc], &Ah[(size_t)(m0 + r) * Kp + k0 + lc]);
                cpa16(&base[1 * AS + r * 20 + lc], &Al[(size_t)(m0 + r) * Kp + k0 + lc]);
                cpa16(&base[2 * AS + r * 20 + lc], &Bh[(size_t)(n0 + r) * Kp + k0 + lc]);
                cpa16(&base[3 * AS + r * 20 + lc], &Bl[(size_t)(n0 + r) * Kp + k0 + lc]);
            }
            CP_COMMIT();
            CP_WAIT1();
        } else {
            CP_WAIT0();
        }
        __syncthreads();

        unsigned* sAh = dsm + st * 4 * AS;
        unsigned* sAl = sAh + AS;
        unsigned* sBh = sAh + 2 * AS;
        unsigned* sBl = sAh + 3 * AS;
#pragma unroll
        for (int kc = 0; kc < 2; kc++) {
            unsigned bhf[4][2], blf[4][2];
#pragma unroll
            for (int ni = 0; ni < 4; ni++) {
                int nb = (wn * 32 + ni * 8 + g) * 20 + kc * 8 + tg;
                bhf[ni][0] = sBh[nb];
                bhf[ni][1] = sBh[nb + 4];
                blf[ni][0] = sBl[nb];
                blf[ni][1] = sBl[nb + 4];
            }
#pragma unroll
            for (int mi = 0; mi < 4; mi++) {
                int r1 = (wm * 64 + mi * 16 + g) * 20 + kc * 8 + tg;
                int r2 = r1 + 8 * 20;
                unsigned ah0 = sAh[r1], ah1 = sAh[r2], ah2 = sAh[r1 + 4], ah3 = sAh[r2 + 4];
                unsigned al0 = sAl[r1], al1 = sAl[r2], al2 = sAl[r1 + 4], al3 = sAl[r2 + 4];
#pragma unroll
                for (int ni = 0; ni < 4; ni++) {
                    MMAB(c[mi][ni], ah0, ah1, ah2, ah3, bhf[ni][0], bhf[ni][1]);
                    MMAB(c[mi][ni], ah0, ah1, ah2, ah3, blf[ni][0], blf[ni][1]);
                    MMAB(c[mi][ni], al0, al1, al2, al3, bhf[ni][0], bhf[ni][1]);
                }
            }
        }
        __syncthreads();
    }

#pragma unroll
    for (int mi = 0; mi < 4; mi++)
#pragma unroll
        for (int ni = 0; ni < 4; ni++) {
            int r = m0 + wm * 64 + mi * 16 + g;
            int col = n0 + wn * 32 + ni * 8 + 2 * tg;
            *(float2*)&Y[(size_t)r * N + col] = make_float2(c[mi][ni][0], c[mi][ni][1]);
            *(float2*)&Y[(size_t)(r + 8) * N + col] = make_float2(c[mi][ni][2], c[mi][ni][3]);
        }
}

// ---------------- fused projections: QK (mixed tf32) + V (bf16x3) ----------
#define PROJ_SMEM (2 * 4 * 128 * 20 * 4)   // 81920 B

__global__ __launch_bounds__(256) void proj_fused(const float* __restrict__ X,
                                                  const float* __restrict__ Wq,
                                                  const float* __restrict__ Wk,
                                                  const float* __restrict__ Xr,
                                                  const float* __restrict__ Wr,
                                                  float* __restrict__ Q,
                                                  float* __restrict__ K,
                                                  float* __restrict__ V) {
    extern __shared__ float fsm[];
    const int xt = blockIdx.x;
    const int m0 = blockIdx.y * 128;

    if (xt < 16) {
        float* Asm = fsm;
        float* Bsm = fsm + 2 * QK_SS;
        float* Y = (xt < 8) ? Q : K;
        const int col0 = (xt & 7) * 128;
        if (xt == 0 || xt == 8) {
            const float* Asrc = X + (size_t)m0 * DMODEL;
            const float* Bsrc = (xt < 8) ? Wq : Wk;
            qk_body<3>(Asrc, Bsrc, Y, m0, col0, Asm, Bsm);
        } else {
            const float* Asrc = Xr + (size_t)m0 * DMODEL;
            const float* Bsrc = Wr + (size_t)xt * 128 * DMODEL;
            qk_body<1>(Asrc, Bsrc, Y, m0, col0, Asm, Bsm);
        }
    } else {
        bf3_body(g_Xh, g_Xl, g_Wvh, g_Wvl, V, m0, (xt - 16) * 128, DMODEL, KP,
                 (unsigned*)fsm);
    }
}

// ---------------- standalone bf16x3 GEMM (output projection) ----------
__global__ __launch_bounds__(256) void gemm_bf3(const unsigned* __restrict__ Ah,
                                                const unsigned* __restrict__ Al,
                                                const unsigned* __restrict__ Bh,
                                                const unsigned* __restrict__ Bl,
                                                float* __restrict__ Y,
                                                int M, int N, int Kp) {
    extern __shared__ unsigned dsm[];
    bf3_body(Ah, Al, Bh, Bl, Y, blockIdx.y * 128, blockIdx.x * 128, N, Kp, dsm);
}

// ---------------- merged LN(Q)+LN(K): identical bodies, one launch ----------------
__global__ __launch_bounds__(256) void ln_qk(float* __restrict__ Q,
                                             float* __restrict__ K,
                                             const float* __restrict__ gq,
                                             const float* __restrict__ bq,
                                             const float* __restrict__ gk,
                                             const float* __restrict__ bk) {
    __shared__ float red[256];
    int row = blockIdx.x;
    float* y;
    const float* g;
    const float* b;
    unsigned* t;
    float scale;
    if (row < MR) {
        y = g_Q + (size_t)row * DMODEL;
        t = g_Qt + (size_t)row * DMODEL;
        g = gq; b = bq; scale = 0.125f;
    } else {
        row -= MR;
        y = g_K + (size_t)row * DMODEL;
        t = g_Kt + (size_t)row * DMODEL;
        g = gk; b = bk; scale = 1.0f;
    }

    float s = 0.f;
    for (int i = threadIdx.x; i < DMODEL; i += 256) s += y[i];
    red[threadIdx.x] = s;
    __syncthreads();
    for (int o = 128; o > 0; o >>= 1) {
        if (threadIdx.x < o) red[threadIdx.x] += red[threadIdx.x + o];
        __syncthreads();
    }
    const float mu = red[0] * (1.0f / DMODEL);
    __syncthreads();

    float v = 0.f;
    for (int i = threadIdx.x; i < DMODEL; i += 256) {
        float d = y[i] - mu;
        v += d * d;
    }
    red[threadIdx.x] = v;
    __syncthreads();
    for (int o = 128; o > 0; o >>= 1) {
        if (threadIdx.x < o) red[threadIdx.x] += red[threadIdx.x + o];
        __syncthreads();
    }
    const float rstd = rsqrtf(red[0] * (1.0f / DMODEL) + 1e-5f);
    __syncthreads();

    for (int i = threadIdx.x; i < DMODEL; i += 256) {
        float val = (y[i] - mu) * rstd * g[i] + b[i];
        y[i] = val;
        t[i] = f2t(val * scale);
    }
}

// ---------------- head-0 scores + fused column sums, vt_split stitched in ----------
// grid.x: [0,16) head0 tiles; [16,48) vt tiles (nt = x-16).
// head0 upper tiles: only g_P zeros (final_scan predicates C loads, rewrites all F).
__global__ __launch_bounds__(256) void head0_vt() {
    __shared__ float As[128][36];
    __shared__ float Bs[128][36];
    __shared__ float cs[128];
    const int tid = threadIdx.x;

    if (blockIdx.x >= 16) {   // ------- vt_split body (uses As as the 64x68 tile) -------
        const int nt = blockIdx.x - 16, h = blockIdx.y, b = blockIdx.z;
        const int n0 = nt * 64;
        float* tile = &As[0][0];   // 64*68 floats = 17408 <= 128*36
#pragma unroll
        for (int t = 0; t < 4; t++) {
            int idx = tid + t * 256;
            int r = idx >> 4, c4 = (idx & 15) * 4;
            *(float4*)&tile[r * 68 + c4] =
                *(const float4*)&g_V[(size_t)(b * SEQL + n0 + r) * DMODEL + h * DHEAD + c4];
        }
        __syncthreads();
#pragma unroll
        for (int t = 0; t < 8; t++) {
            int idx = tid + t * 256;
            int d = idx >> 5, j = idx & 31;
            unsigned hh, ll;
            bsplit(tile[(2 * j) * 68 + d], tile[(2 * j + 1) * 68 + d], hh, ll);
            size_t off = ((size_t)((b * NHEADS + h) * DHEAD + d)) * (SEQL / 2) + (n0 >> 1) + j;
            g_Vth[off] = hh;
            g_Vtl[off] = ll;
        }
        return;
    }

    // ------- head0 body -------
    const int lane = tid & 31, warp = tid >> 5;
    const int g = lane >> 2, tg = lane & 3;
    const int wm = warp >> 2, wn = warp & 3;
    const int bb = blockIdx.z;
    const int r0 = blockIdx.y * 128, mm0 = blockIdx.x * 128;
    const size_t pbase = (size_t)(bb * NSEG + blockIdx.y) * SEQL + mm0;

    if (mm0 >= r0 + 128) {
        if (tid < 128) g_P[pbase + tid] = 0.f;
        return;
    }

    const float* Aq = g_Q + (size_t)(bb * SEQL + r0) * DMODEL;
    const float* Bk = g_K + (size_t)(bb * SEQL + mm0) * DMODEL;
    const int lrow = tid >> 3, lcol = (tid & 7) * 4;

    float c[4][4][4] = {};

    for (int k0 = 0; k0 < 64; k0 += 32) {
#pragma unroll
        for (int it = 0; it < 4; it++) {
            int r = lrow + it * 32;
            *(float4*)&As[r][lcol] = *(const float4*)&Aq[(size_t)r * DMODEL + k0 + lcol];
            *(float4*)&Bs[r][lcol] = *(const float4*)&Bk[(size_t)r * DMODEL + k0 + lcol];
        }
        __syncthreads();
#pragma unroll
        for (int kc = 0; kc < 4; kc++) {
            unsigned bh[4][2], bl[4][2];
#pragma unroll
            for (int ni = 0; ni < 4; ni++) {
                int nb = wn * 32 + ni * 8;
                float b0 = Bs[nb + g][kc * 8 + tg];
                float b1 = Bs[nb + g][kc * 8 + tg + 4];
                bh[ni][0] = f2t(b0);
                bh[ni][1] = f2t(b1);
                bl[ni][0] = f2t(b0 - __uint_as_float(bh[ni][0]));
                bl[ni][1] = f2t(b1 - __uint_as_float(bh[ni][1]));
            }
#pragma unroll
            for (int mi = 0; mi < 4; mi++) {
                int rm = wm * 64 + mi * 16;
                float a0 = As[rm + g][kc * 8 + tg];
                float a1 = As[rm + g + 8][kc * 8 + tg];
                float a2 = As[rm + g][kc * 8 + tg + 4];
                float a3 = As[rm + g + 8][kc * 8 + tg + 4];
                unsigned ah0 = f2t(a0), ah1 = f2t(a1), ah2 = f2t(a2), ah3 = f2t(a3);
                unsigned al0 = f2t(a0 - __uint_as_float(ah0));
                unsigned al1 = f2t(a1 - __uint_as_float(ah1));
                unsigned al2 = f2t(a2 - __uint_as_float(ah2));
                unsigned al3 = f2t(a3 - __uint_as_float(ah3));
#pragma unroll
                for (int ni = 0; ni < 4; ni++) {
                    MMA(c[mi][ni], ah0, ah1, ah2, ah3, bh[ni][0], bh[ni][1]);
                    MMA(c[mi][ni], ah0, ah1, ah2, ah3, bl[ni][0], bl[ni][1]);
                    MMA(c[mi][ni], al0, al1, al2, al3, bh[ni][0], bh[ni][1]);
                }
            }
        }
        __syncthreads();
    }

    if (tid < 128) cs[tid] = 0.f;
    __syncthreads();

    float csl[4][2] = {};
#pragma unroll
    for (int mi = 0; mi < 4; mi++)
#pragma unroll
        for (int ni = 0; ni < 4; ni++) {
            int r1 = r0 + wm * 64 + mi * 16 + g;
            int r2 = r1 + 8;
            int m = mm0 + wn * 32 + ni * 8 + 2 * tg;
            float v0 = c[mi][ni][0] * 0.125f;
            float v1 = c[mi][ni][1] * 0.125f;
            float v2 = c[mi][ni][2] * 0.125f;
            float v3 = c[mi][ni][3] * 0.125f;
            v0 = (m >= 1 && m < r1) ? fmaxf(v0, 0.f) : 0.f;
            v1 = (m + 1 < r1) ? fmaxf(v1, 0.f) : 0.f;
            v2 = (m >= 1 && m < r2) ? fmaxf(v2, 0.f) : 0.f;
            v3 = (m + 1 < r2) ? fmaxf(v3, 0.f) : 0.f;
            *(float2*)&g_F[(size_t)(bb * SEQL + r1) * SEQL + m] = make_float2(v0, v1);
            *(float2*)&g_F[(size_t)(bb * SEQL + r2) * SEQL + m] = make_float2(v2, v3);
            csl[ni][0] += v0 + v2;
            csl[ni][1] += v1 + v3;
        }

#pragma unroll
    for (int ni = 0; ni < 4; ni++)
#pragma unroll
        for (int j = 0; j < 2; j++) {
            float v = csl[ni][j];
            v += __shfl_xor_sync(0xffffffffu, v, 4);
            v += __shfl_xor_sync(0xffffffffu, v, 8);
            v += __shfl_xor_sync(0xffffffffu, v, 16);
            csl[ni][j] = v;
        }
    if (g == 0) {
#pragma unroll
        for (int ni = 0; ni < 4; ni++) {
            atomicAdd(&cs[wn * 32 + ni * 8 + 2 * tg], csl[ni][0]);
            atomicAdd(&cs[wn * 32 + ni * 8 + 2 * tg + 1], csl[ni][1]);
        }
    }
    __syncthreads();
    if (tid < 128) g_P[pbase + tid] = cs[tid];
}

// ---------------- single scan pass ----------------
__global__ __launch_bounds__(256) void final_scan() {
    const int m = blockIdx.x * 256 + threadIdx.x;
    const int seg = blockIdx.y, b = blockIdx.z;
    float acc = 0.f;
    for (int s = 0; s < seg; s++)
        acc += g_P[(size_t)(b * NSEG + s) * SEQL + m];
    float* base = g_F + (size_t)(b * SEQL + seg * SEGROWS) * SEQL + m;
    const int r0 = seg * SEGROWS;
#pragma unroll 4
    for (int r = 0; r < SEGROWS; r++) {
        float c = (r0 + r > m) ? base[(size_t)r * SEQL] : 0.f;
        base[(size_t)r * SEQL] = acc;
        acc += c;
    }
}

// ---------------- flash attention: BM=64, 128 threads, cp.async K/V ----------
#define ATTN_KSZ  (64 * 68)
#define ATTN_VSZ  (64 * 36)
#define ATTN_VHOFF (2 * ATTN_KSZ)
#define ATTN_VLOFF (2 * ATTN_KSZ + 2 * ATTN_VSZ)
#define ATTN_SMEM  ((2 * ATTN_KSZ + 4 * ATTN_VSZ) * 4)

__global__ __launch_bounds__(128) void attn_bf() {
    extern __shared__ unsigned sm[];
    const int b = blockIdx.z, h = blockIdx.y;
    const int qt = (int)gridDim.x - 1 - (int)blockIdx.x;
    const int q0 = qt * 64;
    const int tid = threadIdx.x, lane = tid & 31, w = tid >> 5;
    const int g = lane >> 2, tg = lane & 3;

    unsigned qa[8][4];
    const size_t qr1 = (size_t)(b * SEQL + q0 + w * 16 + g) * DMODEL + h * DHEAD;
    const size_t qr2 = qr1 + 8 * DMODEL;
#pragma unroll
    for (int kc = 0; kc < 8; kc++) {
        qa[kc][0] = g_Qt[qr1 + kc * 8 + tg];
        qa[kc][1] = g_Qt[qr2 + kc * 8 + tg];
        qa[kc][2] = g_Qt[qr1 + kc * 8 + tg + 4];
        qa[kc][3] = g_Qt[qr2 + kc * 8 + tg + 4];
    }

    float o[8][4] = {};
    float qm0 = -1e30f, qm1 = -1e30f, lsum0 = 0.f, lsum1 = 0.f;

    {
        const size_t kbase = (size_t)(b * SEQL) * DMODEL + h * DHEAD;
        const size_t vbase = (size_t)((b * NHEADS + h) * DHEAD) * (SEQL / 2);
#pragma unroll
        for (int t = 0; t < 8; t++) {
            int idx = tid + t * 128;
            int r = idx >> 4, c4 = (idx & 15) * 4;
            cpa16(&sm[r * 68 + c4], &g_Kt[kbase + (size_t)r * DMODEL + c4]);
        }
#pragma unroll
        for (int t = 0; t < 4; t++) {
            int idx = tid + t * 128;
            int r = idx >> 3, c4 = (idx & 7) * 4;
            cpa16(&sm[ATTN_VHOFF + r * 36 + c4], &g_Vth[vbase + (size_t)r * (SEQL / 2) + c4]);
            cpa16(&sm[ATTN_VLOFF + r * 36 + c4], &g_Vtl[vbase + (size_t)r * (SEQL / 2) + c4]);
        }
        CP_COMMIT();
    }

    for (int kt = 0; kt <= qt; kt++) {
        const int buf = kt & 1;
        const int m0 = kt * 64;
        if (kt < qt) {
            const int m0n = m0 + 64;
            const int nb = buf ^ 1;
            const size_t kbase = (size_t)(b * SEQL + m0n) * DMODEL + h * DHEAD;
            const size_t vbase = (size_t)((b * NHEADS + h) * DHEAD) * (SEQL / 2) + (m0n >> 1);
#pragma unroll
            for (int t = 0; t < 8; t++) {
                int idx = tid + t * 128;
                int r = idx >> 4, c4 = (idx & 15) * 4;
                cpa16(&sm[nb * ATTN_KSZ + r * 68 + c4], &g_Kt[kbase + (size_t)r * DMODEL + c4]);
            }
#pragma unroll
            for (int t = 0; t < 4; t++) {
                int idx = tid + t * 128;
                int r = idx >> 3, c4 = (idx & 7) * 4;
                cpa16(&sm[ATTN_VHOFF + nb * ATTN_VSZ + r * 36 + c4],
                      &g_Vth[vbase + (size_t)r * (SEQL / 2) + c4]);
                cpa16(&sm[ATTN_VLOFF + nb * ATTN_VSZ + r * 36 + c4],
                      &g_Vtl[vbase + (size_t)r * (SEQL / 2) + c4]);
            }
            CP_COMMIT();
            CP_WAIT1();
        } else {
            CP_WAIT0();
        }
        __syncthreads();

        const unsigned* sKt = sm + buf * ATTN_KSZ;
        const unsigned* sVh = sm + ATTN_VHOFF + buf * ATTN_VSZ;
        const unsigned* sVl = sm + ATTN_VLOFF + buf * ATTN_VSZ;

        float sc[8][4] = {};
#pragma unroll
        for (int kc = 0; kc < 8; kc++) {
#pragma unroll
            for (int ni = 0; ni < 8; ni++) {
                unsigned b0 = sKt[(ni * 8 + g) * 68 + kc * 8 + tg];
                unsigned b1 = sKt[(ni * 8 + g) * 68 + kc * 8 + tg + 4];
                MMA(sc[ni], qa[kc][0], qa[kc][1], qa[kc][2], qa[kc][3], b0, b1);
            }
        }

        const bool diag = (kt == qt);
        const int lr1 = w * 16 + g, lr2 = lr1 + 8;
        const size_t frow1 = (size_t)(b * SEQL + q0 + lr1) * SEQL + m0;
        const size_t frow2 = (size_t)(b * SEQL + q0 + lr2) * SEQL + m0;
        float mx0 = -1e30f, mx1 = -1e30f;
#pragma unroll
        for (int ni = 0; ni < 8; ni++) {
            int cl = ni * 8 + 2 * tg;
            float2 f1 = *(const float2*)&g_F[frow1 + cl];
            float2 f2 = *(const float2*)&g_F[frow2 + cl];
            float v0 = sc[ni][0] - f1.x;
            float v1 = sc[ni][1] - f1.y;
            float v2 = sc[ni][2] - f2.x;
            float v3 = sc[ni][3] - f2.y;
            if (diag) {
                if (cl > lr1) v0 = -1e30f;
                if (cl + 1 > lr1) v1 = -1e30f;
                if (cl > lr2) v2 = -1e30f;
                if (cl + 1 > lr2) v3 = -1e30f;
            }
            sc[ni][0] = v0; sc[ni][1] = v1; sc[ni][2] = v2; sc[ni][3] = v3;
            mx0 = fmaxf(mx0, fmaxf(v0, v1));
            mx1 = fmaxf(mx1, fmaxf(v2, v3));
        }
        mx0 = fmaxf(mx0, __shfl_xor_sync(0xffffffffu, mx0, 1));
        mx0 = fmaxf(mx0, __shfl_xor_sync(0xffffffffu, mx0, 2));
        mx1 = fmaxf(mx1, __shfl_xor_sync(0xffffffffu, mx1, 1));
        mx1 = fmaxf(mx1, __shfl_xor_sync(0xffffffffu, mx1, 2));
        const float nm0 = fmaxf(qm0, mx0), nm1 = fmaxf(qm1, mx1);
        const float s0 = __expf(qm0 - nm0), s1 = __expf(qm1 - nm1);
        float ps0 = 0.f, ps1 = 0.f;
#pragma unroll
        for (int ni = 0; ni < 8; ni++) {
            float e0 = __expf(sc[ni][0] - nm0);
            float e1 = __expf(sc[ni][1] - nm0);
            float e2 = __expf(sc[ni][2] - nm1);
            float e3 = __expf(sc[ni][3] - nm1);
            sc[ni][0] = e0; sc[ni][1] = e1; sc[ni][2] = e2; sc[ni][3] = e3;
            ps0 += e0 + e1;
            ps1 += e2 + e3;
            o[ni][0] *= s0; o[ni][1] *= s0; o[ni][2] *= s1; o[ni][3] *= s1;
        }
        ps0 += __shfl_xor_sync(0xffffffffu, ps0, 1);
        ps0 += __shfl_xor_sync(0xffffffffu, ps0, 2);
        ps1 += __shfl_xor_sync(0xffffffffu, ps1, 1);
        ps1 += __shfl_xor_sync(0xffffffffu, ps1, 2);
        lsum0 = lsum0 * s0 + ps0;
        lsum1 = lsum1 * s1 + ps1;
        qm0 = nm0; qm1 = nm1;

#pragma unroll
        for (int kc2 = 0; kc2 < 4; kc2++) {
            unsigned ph0, pl0, ph1, pl1, ph2, pl2, ph3, pl3;
            bsplit(sc[kc2 * 2][0], sc[kc2 * 2][1], ph0, pl0);
            bsplit(sc[kc2 * 2][2], sc[kc2 * 2][3], ph1, pl1);
            bsplit(sc[kc2 * 2 + 1][0], sc[kc2 * 2 + 1][1], ph2, pl2);
            bsplit(sc[kc2 * 2 + 1][2], sc[kc2 * 2 + 1][3], ph3, pl3);
#pragma unroll
            for (int ni = 0; ni < 8; ni++) {
                int vb = (ni * 8 + g) * 36 + kc2 * 8 + tg;
                unsigned vh0 = sVh[vb], vh1 = sVh[vb + 4];
                unsigned vl0 = sVl[vb], vl1 = sVl[vb + 4];
                MMAB(o[ni], ph0, ph1, ph2, ph3, vh0, vh1);
                MMAB(o[ni], ph0, ph1, ph2, ph3, vl0, vl1);
                MMAB(o[ni], pl0, pl1, pl2, pl3, vh0, vh1);
            }
        }
        __syncthreads();
    }

    const float i0 = 1.0f / lsum0, i1 = 1.0f / lsum1;
    const size_t or1 = (size_t)(b * SEQL + q0 + w * 16 + g) * KP + h * 32;
    const size_t or2 = or1 + 8 * KP;
#pragma unroll
    for (int ni = 0; ni < 8; ni++) {
        unsigned hh, ll;
        bsplit(o[ni][0] * i0, o[ni][1] * i0, hh, ll);
        g_Oh[or1 + ni * 4 + tg] = hh;
        g_Ol[or1 + ni * 4 + tg] = ll;
        bsplit(o[ni][2] * i1, o[ni][3] * i1, hh, ll);
        g_Oh[or2 + ni * 4 + tg] = hh;
        g_Ol[or2 + ni * 4 + tg] = ll;
    }
}

// ---------------- launch ----------------
extern "C" void kernel_launch(void* const* d_in, const int* in_sizes, int n_in,
                              void* d_out, int out_size) {
    const float* X  = (const float*)d_in[0];
    const float* Wq = (const float*)d_in[1];
    const float* Wk = (const float*)d_in[2];
    const float* Wv = (const float*)d_in[3];
    const float* Wo = (const float*)d_in[4];
    const float* gq = (const float*)d_in[5];
    const float* bq = (const float*)d_in[6];
    const float* gk = (const float*)d_in[7];
    const float* bk = (const float*)d_in[8];
    float* out = (float*)d_out;

    float *pQ, *pK, *pV, *pXr, *pWr;
    unsigned *pWoh, *pWol, *pOh, *pOl;
    cudaGetSymbolAddress((void**)&pQ, g_Q);
    cudaGetSymbolAddress((void**)&pK, g_K);
    cudaGetSymbolAddress((void**)&pV, g_V);
    cudaGetSymbolAddress((void**)&pXr, g_Xr);
    cudaGetSymbolAddress((void**)&pWr, g_Wr);
    cudaGetSymbolAddress((void**)&pWoh, g_Woh);
    cudaGetSymbolAddress((void**)&pWol, g_Wol);
    cudaGetSymbolAddress((void**)&pOh, g_Oh);
    cudaGetSymbolAddress((void**)&pOl, g_Ol);

    cudaFuncSetAttribute(proj_fused, cudaFuncAttributeMaxDynamicSharedMemorySize, PROJ_SMEM);
    cudaFuncSetAttribute(gemm_bf3, cudaFuncAttributeMaxDynamicSharedMemorySize, PROJ_SMEM);
    cudaFuncSetAttribute(attn_bf, cudaFuncAttributeMaxDynamicSharedMemorySize, ATTN_SMEM);

    prepass<<<(PRE_TOT + 255) / 256, 256>>>(X, Wv, Wo, Wq, Wk);

    proj_fused<<<dim3(24, MR / 128), 256, PROJ_SMEM>>>(X, Wq, Wk, pXr, pWr, pQ, pK, pV);

    ln_qk<<<2 * MR, 256>>>(pQ, pK, gq, bq, gk, bk);

    // head0 scores + fused segment sums + vt_split co-scheduled in one grid
    head0_vt<<<dim3(16 + SEQL / 64, NSEG, BATCH), 256>>>();
    final_scan<<<dim3(SEQL / 256, NSEG, BATCH), 256>>>();

    attn_bf<<<dim3(SEQL / 64, NHEADS, BATCH), 128, ATTN_SMEM>>>();

    gemm_bf3<<<dim3(DMODEL / 128, MR / 128), 256, PROJ_SMEM>>>(pOh, pOl, pWoh, pWol, out,
                                                               MR, DMODEL, KP);
}

// round 16
// speedup vs baseline: 1.0215x; 1.0032x over previous
#include <cuda_runtime.h>
#include <cuda_bf16.h>
#include <math.h>

#define SEQL   2048
#define BATCH  2
#define DMODEL 1024
#define NHEADS 16
#define DHEAD  64
#define MR     (BATCH * SEQL)   // 4096 rows
#define NSEG   16
#define SEGROWS (SEQL / NSEG)   // 128
#define KP     (DMODEL / 2)     // 512 bf16-pair columns
#define LOG2E  1.4426950408889634f

// ---------------- scratch ----------------
__device__ float    g_Q[(size_t)MR * DMODEL];
__device__ float    g_K[(size_t)MR * DMODEL];
__device__ float    g_V[(size_t)MR * DMODEL];
__device__ float    g_Xr[(size_t)MR * DMODEL];         // tf32-rounded X (x1 path)
__device__ float    g_Wr[(size_t)2 * DMODEL * DMODEL]; // Wq then Wk, rounded
__device__ unsigned g_Qt[(size_t)MR * DMODEL];         // tf32 bits, PRE-SCALED by 0.125*log2e
__device__ unsigned g_Kt[(size_t)MR * DMODEL];
__device__ unsigned g_Xh[(size_t)MR * KP];
__device__ unsigned g_Xl[(size_t)MR * KP];
__device__ unsigned g_Wvh[(size_t)DMODEL * KP];
__device__ unsigned g_Wvl[(size_t)DMODEL * KP];
__device__ unsigned g_Woh[(size_t)DMODEL * KP];
__device__ unsigned g_Wol[(size_t)DMODEL * KP];
__device__ unsigned g_Vth[(size_t)BATCH * NHEADS * DHEAD * (SEQL / 2)];
__device__ unsigned g_Vtl[(size_t)BATCH * NHEADS * DHEAD * (SEQL / 2)];
__device__ unsigned g_Oh[(size_t)MR * KP];
__device__ unsigned g_Ol[(size_t)MR * KP];
__device__ float    g_F[(size_t)BATCH * SEQL * SEQL];
__device__ float    g_P[(size_t)BATCH * NSEG * SEQL];

// ---------------- helpers ----------------
__device__ __forceinline__ unsigned f2t(float x) {
    unsigned r;
    asm("cvt.rna.tf32.f32 %0, %1;" : "=r"(r) : "f"(x));
    return r;
}

__device__ __forceinline__ float ex2(float x) {
    float r;
    asm("ex2.approx.f32 %0, %1;" : "=f"(r) : "f"(x));
    return r;
}

__device__ __forceinline__ void bsplit(float x0, float x1, unsigned& h, unsigned& l) {
    asm("cvt.rn.bf16x2.f32 %0, %1, %2;" : "=r"(h) : "f"(x1), "f"(x0));
    __nv_bfloat162 hb = *reinterpret_cast<__nv_bfloat162*>(&h);
    float2 hf = __bfloat1622float2(hb);
    float r0 = x0 - hf.x, r1 = x1 - hf.y;
    asm("cvt.rn.bf16x2.f32 %0, %1, %2;" : "=r"(l) : "f"(r1), "f"(r0));
}

__device__ __forceinline__ void cpa16(void* smem, const void* gmem) {
    unsigned s = (unsigned)__cvta_generic_to_shared(smem);
    asm volatile("cp.async.cg.shared.global [%0], [%1], 16;" :: "r"(s), "l"(gmem));
}
#define CP_COMMIT() asm volatile("cp.async.commit_group;")
#define CP_WAIT1()  asm volatile("cp.async.wait_group 1;")
#define CP_WAIT0()  asm volatile("cp.async.wait_group 0;")

#define MMA(C, A0, A1, A2, A3, B0, B1)                                         \
    asm volatile(                                                              \
        "mma.sync.aligned.m16n8k8.row.col.f32.tf32.tf32.f32 "                  \
        "{%0,%1,%2,%3},{%4,%5,%6,%7},{%8,%9},{%0,%1,%2,%3};"                   \
        : "+f"((C)[0]), "+f"((C)[1]), "+f"((C)[2]), "+f"((C)[3])               \
        : "r"(A0), "r"(A1), "r"(A2), "r"(A3), "r"(B0), "r"(B1))

#define MMAB(C, A0, A1, A2, A3, B0, B1)                                        \
    asm volatile(                                                              \
        "mma.sync.aligned.m16n8k16.row.col.f32.bf16.bf16.f32 "                 \
        "{%0,%1,%2,%3},{%4,%5,%6,%7},{%8,%9},{%0,%1,%2,%3};"                   \
        : "+f"((C)[0]), "+f"((C)[1]), "+f"((C)[2]), "+f"((C)[3])               \
        : "r"(A0), "r"(A1), "r"(A2), "r"(A3), "r"(B0), "r"(B1))

// ---------------- mega prepass ----------------
#define PRE_N0 (MR * KP)
#define PRE_N1 (DMODEL * KP)
#define PRE_TOT (PRE_N0 + 4 * PRE_N1)

__global__ __launch_bounds__(256) void prepass(const float* __restrict__ X,
                                               const float* __restrict__ Wv,
                                               const float* __restrict__ Wo,
                                               const float* __restrict__ Wq,
                                               const float* __restrict__ Wk) {
    int i = blockIdx.x * 256 + threadIdx.x;
    if (i < PRE_N0) {
        float2 v = ((const float2*)X)[i];
        unsigned hh, ll;
        bsplit(v.x, v.y, hh, ll);
        g_Xh[i] = hh;
        g_Xl[i] = ll;
        float2 o;
        o.x = __uint_as_float(f2t(v.x));
        o.y = __uint_as_float(f2t(v.y));
        ((float2*)g_Xr)[i] = o;
        return;
    }
    i -= PRE_N0;
    if (i < PRE_N1) {
        float2 v = ((const float2*)Wv)[i];
        unsigned hh, ll;
        bsplit(v.x, v.y, hh, ll);
        g_Wvh[i] = hh;
        g_Wvl[i] = ll;
        return;
    }
    i -= PRE_N1;
    if (i < PRE_N1) {
        float2 v = ((const float2*)Wo)[i];
        unsigned hh, ll;
        bsplit(v.x, v.y, hh, ll);
        g_Woh[i] = hh;
        g_Wol[i] = ll;
        return;
    }
    i -= PRE_N1;
    if (i < PRE_N1) {
        float2 v = ((const float2*)Wq)[i];
        float2 o;
        o.x = __uint_as_float(f2t(v.x));
        o.y = __uint_as_float(f2t(v.y));
        ((float2*)g_Wr)[i] = o;
        return;
    }
    i -= PRE_N1;
    if (i < PRE_N1) {
        float2 v = ((const float2*)Wk)[i];
        float2 o;
        o.x = __uint_as_float(f2t(v.x));
        o.y = __uint_as_float(f2t(v.y));
        ((float2*)(g_Wr + (size_t)DMODEL * DMODEL))[i] = o;
    }
}

// ---------------- qk tile body (BK=32, 2-stage, mixed split) ----------------
#define QK_SS   (128 * 36)

template <int SPLIT>
__device__ __forceinline__ void qk_body(const float* __restrict__ Asrc,
                                        const float* __restrict__ Bsrc,
                                        float* __restrict__ Y,
                                        int m0, int col0,
                                        float* __restrict__ Asm,
                                        float* __restrict__ Bsm) {
    const int tid = threadIdx.x, lane = tid & 31, warp = tid >> 5;
    const int g = lane >> 2, tg = lane & 3;
    const int wm = warp >> 2, wn = warp & 3;

    float c[4][4][4] = {};

#define QK_LOAD(stage, k0)                                                     \
    do {                                                                       \
        float* As_ = Asm + (stage) * QK_SS;                                    \
        float* Bs_ = Bsm + (stage) * QK_SS;                                    \
        _Pragma("unroll")                                                      \
        for (int t = 0; t < 4; t++) {                                          \
            int idx = tid + t * 256;                                           \
            int r = idx >> 3, c4 = (idx & 7) * 4;                              \
            cpa16(&As_[r * 36 + c4], &Asrc[(size_t)r * DMODEL + (k0) + c4]);   \
            cpa16(&Bs_[r * 36 + c4], &Bsrc[(size_t)r * DMODEL + (k0) + c4]);   \
        }                                                                      \
    } while (0)

    QK_LOAD(0, 0);
    CP_COMMIT();

    const int nIt = DMODEL / 32;
    for (int it = 0; it < nIt; it++) {
        const int st = it & 1;
        if (it + 1 < nIt) {
            QK_LOAD(st ^ 1, (it + 1) * 32);
            CP_COMMIT();
            CP_WAIT1();
        } else {
            CP_WAIT0();
        }
        __syncthreads();

        const float* As_ = Asm + st * QK_SS;
        const float* Bs_ = Bsm + st * QK_SS;
#pragma unroll
        for (int kc = 0; kc < 4; kc++) {
            unsigned bh[4][2], bl[4][2];
#pragma unroll
            for (int ni = 0; ni < 4; ni++) {
                int nb = (wn * 32 + ni * 8 + g) * 36 + kc * 8 + tg;
                float b0 = Bs_[nb];
                float b1 = Bs_[nb + 4];
                if (SPLIT == 3) {
                    bh[ni][0] = f2t(b0);
                    bh[ni][1] = f2t(b1);
                    bl[ni][0] = f2t(b0 - __uint_as_float(bh[ni][0]));
                    bl[ni][1] = f2t(b1 - __uint_as_float(bh[ni][1]));
                } else {
                    bh[ni][0] = __float_as_uint(b0);
                    bh[ni][1] = __float_as_uint(b1);
                }
            }
#pragma unroll
            for (int mi = 0; mi < 4; mi++) {
                int r1 = (wm * 64 + mi * 16 + g) * 36 + kc * 8 + tg;
                int r2 = r1 + 8 * 36;
                float a0 = As_[r1];
                float a1 = As_[r2];
                float a2 = As_[r1 + 4];
                float a3 = As_[r2 + 4];
                unsigned ah0, ah1, ah2, ah3;
                unsigned al0 = 0, al1 = 0, al2 = 0, al3 = 0;
                if (SPLIT == 3) {
                    ah0 = f2t(a0); ah1 = f2t(a1); ah2 = f2t(a2); ah3 = f2t(a3);
                    al0 = f2t(a0 - __uint_as_float(ah0));
                    al1 = f2t(a1 - __uint_as_float(ah1));
                    al2 = f2t(a2 - __uint_as_float(ah2));
                    al3 = f2t(a3 - __uint_as_float(ah3));
                } else {
                    ah0 = __float_as_uint(a0); ah1 = __float_as_uint(a1);
                    ah2 = __float_as_uint(a2); ah3 = __float_as_uint(a3);
                }
#pragma unroll
                for (int ni = 0; ni < 4; ni++) {
                    MMA(c[mi][ni], ah0, ah1, ah2, ah3, bh[ni][0], bh[ni][1]);
                    if (SPLIT == 3) {
                        MMA(c[mi][ni], ah0, ah1, ah2, ah3, bl[ni][0], bl[ni][1]);
                        MMA(c[mi][ni], al0, al1, al2, al3, bh[ni][0], bh[ni][1]);
                    }
                }
            }
        }
        __syncthreads();
    }
#undef QK_LOAD

#pragma unroll
    for (int mi = 0; mi < 4; mi++)
#pragma unroll
        for (int ni = 0; ni < 4; ni++) {
            int r = m0 + wm * 64 + mi * 16 + g;
            int col = col0 + wn * 32 + ni * 8 + 2 * tg;
            *(float2*)&Y[(size_t)r * DMODEL + col] = make_float2(c[mi][ni][0], c[mi][ni][1]);
            *(float2*)&Y[(size_t)(r + 8) * DMODEL + col] = make_float2(c[mi][ni][2], c[mi][ni][3]);
        }
}

// ---------------- bf16x3 tile body ----------------
__device__ __forceinline__ void bf3_body(const unsigned* __restrict__ Ah,
                                         const unsigned* __restrict__ Al,
                                         const unsigned* __restrict__ Bh,
                                         const unsigned* __restrict__ Bl,
                                         float* __restrict__ Y,
                                         int m0, int n0, int N, int Kp,
                                         unsigned* __restrict__ dsm) {
    const int AS = 128 * 20;
    const int tid = threadIdx.x, lane = tid & 31, warp = tid >> 5;
    const int g = lane >> 2, tg = lane & 3;
    const int wm = warp >> 2, wn = warp & 3;
    const int lr = tid >> 2, lc = (tid & 3) * 4;

    float c[4][4][4] = {};

    {
        unsigned* base = dsm;
#pragma unroll
        for (int t = 0; t < 2; t++) {
            int r = lr + t * 64;
            cpa16(&base[0 * AS + r * 20 + lc], &Ah[(size_t)(m0 + r) * Kp + lc]);
            cpa16(&base[1 * AS + r * 20 + lc], &Al[(size_t)(m0 + r) * Kp + lc]);
            cpa16(&base[2 * AS + r * 20 + lc], &Bh[(size_t)(n0 + r) * Kp + lc]);
            cpa16(&base[3 * AS + r * 20 + lc], &Bl[(size_t)(n0 + r) * Kp + lc]);
        }
        CP_COMMIT();
    }

    const int nIt = Kp / 16;
    for (int it = 0; it < nIt; it++) {
        const int st = it & 1;
        if (it + 1 < nIt) {
            const int k0 = (it + 1) * 16;
            unsigned* base = dsm + (st ^ 1) * 4 * AS;
#pragma unroll
            for (int t = 0; t < 2; t++) {
                int r = lr + t * 64;
                cpa16(&base[0 * AS + r * 20 + lc], &Ah[(size_t)(m0 + r) * Kp + k0 + lc]);
                cpa16(&base[1 * AS + r * 20 + lc], &Al[(size_t)(m0 + r) * Kp + k0 + lc]);
                cpa16(&base[2 * AS + r * 20 + lc], &Bh[(size_t)(n0 + r) * Kp + k0 + lc]);
                cpa16(&base[3 * AS + r * 20 + lc], &Bl[(size_t)(n0 + r) * Kp + k0 + lc]);
            }
            CP_COMMIT();
            CP_WAIT1();
        } else {
            CP_WAIT0();
        }
        __syncthreads();

        unsigned* sAh = dsm + st * 4 * AS;
        unsigned* sAl = sAh + AS;
        unsigned* sBh = sAh + 2 * AS;
        unsigned* sBl = sAh + 3 * AS;
#pragma unroll
        for (int kc = 0; kc < 2; kc++) {
            unsigned bhf[4][2], blf[4][2];
#pragma unroll
            for (int ni = 0; ni < 4; ni++) {
                int nb = (wn * 32 + ni * 8 + g) * 20 + kc * 8 + tg;
                bhf[ni][0] = sBh[nb];
                bhf[ni][1] = sBh[nb + 4];
                blf[ni][0] = sBl[nb];
                blf[ni][1] = sBl[nb + 4];
            }
#pragma unroll
            for (int mi = 0; mi < 4; mi++) {
                int r1 = (wm * 64 + mi * 16 + g) * 20 + kc * 8 + tg;
                int r2 = r1 + 8 * 20;
                unsigned ah0 = sAh[r1], ah1 = sAh[r2], ah2 = sAh[r1 + 4], ah3 = sAh[r2 + 4];
                unsigned al0 = sAl[r1], al1 = sAl[r2], al2 = sAl[r1 + 4], al3 = sAl[r2 + 4];
#pragma unroll
                for (int ni = 0; ni < 4; ni++) {
                    MMAB(c[mi][ni], ah0, ah1, ah2, ah3, bhf[ni][0], bhf[ni][1]);
                    MMAB(c[mi][ni], ah0, ah1, ah2, ah3, blf[ni][0], blf[ni][1]);
                    MMAB(c[mi][ni], al0, al1, al2, al3, bhf[ni][0], bhf[ni][1]);
                }
            }
        }
        __syncthreads();
    }

#pragma unroll
    for (int mi = 0; mi < 4; mi++)
#pragma unroll
        for (int ni = 0; ni < 4; ni++) {
            int r = m0 + wm * 64 + mi * 16 + g;
            int col = n0 + wn * 32 + ni * 8 + 2 * tg;
            *(float2*)&Y[(size_t)r * N + col] = make_float2(c[mi][ni][0], c[mi][ni][1]);
            *(float2*)&Y[(size_t)(r + 8) * N + col] = make_float2(c[mi][ni][2], c[mi][ni][3]);
        }
}

// ---------------- fused projections: QK (mixed tf32) + V (bf16x3) ----------
#define PROJ_SMEM (2 * 4 * 128 * 20 * 4)   // 81920 B

__global__ __launch_bounds__(256) void proj_fused(const float* __restrict__ X,
                                                  const float* __restrict__ Wq,
                                                  const float* __restrict__ Wk,
                                                  const float* __restrict__ Xr,
                                                  const float* __restrict__ Wr,
                                                  float* __restrict__ Q,
                                                  float* __restrict__ K,
                                                  float* __restrict__ V) {
    extern __shared__ float fsm[];
    const int xt = blockIdx.x;
    const int m0 = blockIdx.y * 128;

    if (xt < 16) {
        float* Asm = fsm;
        float* Bsm = fsm + 2 * QK_SS;
        float* Y = (xt < 8) ? Q : K;
        const int col0 = (xt & 7) * 128;
        if (xt == 0 || xt == 8) {
            const float* Asrc = X + (size_t)m0 * DMODEL;
            const float* Bsrc = (xt < 8) ? Wq : Wk;
            qk_body<3>(Asrc, Bsrc, Y, m0, col0, Asm, Bsm);
        } else {
            const float* Asrc = Xr + (size_t)m0 * DMODEL;
            const float* Bsrc = Wr + (size_t)xt * 128 * DMODEL;
            qk_body<1>(Asrc, Bsrc, Y, m0, col0, Asm, Bsm);
        }
    } else {
        bf3_body(g_Xh, g_Xl, g_Wvh, g_Wvl, V, m0, (xt - 16) * 128, DMODEL, KP,
                 (unsigned*)fsm);
    }
}

// ---------------- standalone bf16x3 GEMM (output projection) ----------
__global__ __launch_bounds__(256) void gemm_bf3(const unsigned* __restrict__ Ah,
                                                const unsigned* __restrict__ Al,
                                                const unsigned* __restrict__ Bh,
                                                const unsigned* __restrict__ Bl,
                                                float* __restrict__ Y,
                                                int M, int N, int Kp) {
    extern __shared__ unsigned dsm[];
    bf3_body(Ah, Al, Bh, Bl, Y, blockIdx.y * 128, blockIdx.x * 128, N, Kp, dsm);
}

// ---------------- merged LN(Q)+LN(K): one-pass moments, shuffle reduce ----------------
__global__ __launch_bounds__(256) void ln_qk(float* __restrict__ Q,
                                             float* __restrict__ K,
                                             const float* __restrict__ gq,
                                             const float* __restrict__ bq,
                                             const float* __restrict__ gk,
                                             const float* __restrict__ bk) {
    __shared__ float red[16];
    __shared__ float mvs[2];
    int row = blockIdx.x;
    float* y;
    const float* g;
    const float* b;
    unsigned* t;
    float scale;
    if (row < MR) {
        y = g_Q + (size_t)row * DMODEL;
        t = g_Qt + (size_t)row * DMODEL;
        g = gq; b = bq; scale = 0.125f * LOG2E;   // logits land in log2 domain
    } else {
        row -= MR;
        y = g_K + (size_t)row * DMODEL;
        t = g_Kt + (size_t)row * DMODEL;
        g = gk; b = bk; scale = 1.0f;
    }
    const int lane = threadIdx.x & 31, warp = threadIdx.x >> 5;

    float s1 = 0.f, s2 = 0.f;
    for (int i = threadIdx.x; i < DMODEL; i += 256) {
        float x = y[i];
        s1 += x;
        s2 = fmaf(x, x, s2);
    }
#pragma unroll
    for (int d = 16; d; d >>= 1) {
        s1 += __shfl_xor_sync(0xffffffffu, s1, d);
        s2 += __shfl_xor_sync(0xffffffffu, s2, d);
    }
    if (lane == 0) {
        red[warp] = s1;
        red[8 + warp] = s2;
    }
    __syncthreads();
    if (threadIdx.x < 32) {
        float a = (lane < 8) ? red[lane] : 0.f;
        float c2 = (lane < 8) ? red[8 + lane] : 0.f;
#pragma unroll
        for (int d = 4; d; d >>= 1) {
            a += __shfl_xor_sync(0xffffffffu, a, d);
            c2 += __shfl_xor_sync(0xffffffffu, c2, d);
        }
        if (lane == 0) {
            float mu = a * (1.0f / DMODEL);
            float var = c2 * (1.0f / DMODEL) - mu * mu;
            mvs[0] = mu;
            mvs[1] = rsqrtf(var + 1e-5f);
        }
    }
    __syncthreads();
    const float mu = mvs[0], rstd = mvs[1];

    for (int i = threadIdx.x; i < DMODEL; i += 256) {
        float val = (y[i] - mu) * rstd * g[i] + b[i];
        y[i] = val;
        t[i] = f2t(val * scale);
    }
}

// ---------------- head-0 scores + fused column sums, vt_split stitched in ----------
__global__ __launch_bounds__(256) void head0_vt() {
    __shared__ float As[128][36];
    __shared__ float Bs[128][36];
    __shared__ float cs[128];
    const int tid = threadIdx.x;

    if (blockIdx.x >= 16) {   // ------- vt_split body -------
        const int nt = blockIdx.x - 16, h = blockIdx.y, b = blockIdx.z;
        const int n0 = nt * 64;
        float* tile = &As[0][0];
#pragma unroll
        for (int t = 0; t < 4; t++) {
            int idx = tid + t * 256;
            int r = idx >> 4, c4 = (idx & 15) * 4;
            *(float4*)&tile[r * 68 + c4] =
                *(const float4*)&g_V[(size_t)(b * SEQL + n0 + r) * DMODEL + h * DHEAD + c4];
        }
        __syncthreads();
#pragma unroll
        for (int t = 0; t < 8; t++) {
            int idx = tid + t * 256;
            int d = idx >> 5, j = idx & 31;
            unsigned hh, ll;
            bsplit(tile[(2 * j) * 68 + d], tile[(2 * j + 1) * 68 + d], hh, ll);
            size_t off = ((size_t)((b * NHEADS + h) * DHEAD + d)) * (SEQL / 2) + (n0 >> 1) + j;
            g_Vth[off] = hh;
            g_Vtl[off] = ll;
        }
        return;
    }

    // ------- head0 body -------
    const int lane = tid & 31, warp = tid >> 5;
    const int g = lane >> 2, tg = lane & 3;
    const int wm = warp >> 2, wn = warp & 3;
    const int bb = blockIdx.z;
    const int r0 = blockIdx.y * 128, mm0 = blockIdx.x * 128;
    const size_t pbase = (size_t)(bb * NSEG + blockIdx.y) * SEQL + mm0;

    if (mm0 >= r0 + 128) {
        if (tid < 128) g_P[pbase + tid] = 0.f;
        return;
    }

    const float* Aq = g_Q + (size_t)(bb * SEQL + r0) * DMODEL;
    const float* Bk = g_K + (size_t)(bb * SEQL + mm0) * DMODEL;
    const int lrow = tid >> 3, lcol = (tid & 7) * 4;

    float c[4][4][4] = {};

    for (int k0 = 0; k0 < 64; k0 += 32) {
#pragma unroll
        for (int it = 0; it < 4; it++) {
            int r = lrow + it * 32;
            *(float4*)&As[r][lcol] = *(const float4*)&Aq[(size_t)r * DMODEL + k0 + lcol];
            *(float4*)&Bs[r][lcol] = *(const float4*)&Bk[(size_t)r * DMODEL + k0 + lcol];
        }
        __syncthreads();
#pragma unroll
        for (int kc = 0; kc < 4; kc++) {
            unsigned bh[4][2], bl[4][2];
#pragma unroll
            for (int ni = 0; ni < 4; ni++) {
                int nb = wn * 32 + ni * 8;
                float b0 = Bs[nb + g][kc * 8 + tg];
                float b1 = Bs[nb + g][kc * 8 + tg + 4];
                bh[ni][0] = f2t(b0);
                bh[ni][1] = f2t(b1);
                bl[ni][0] = f2t(b0 - __uint_as_float(bh[ni][0]));
                bl[ni][1] = f2t(b1 - __uint_as_float(bh[ni][1]));
            }
#pragma unroll
            for (int mi = 0; mi < 4; mi++) {
                int rm = wm * 64 + mi * 16;
                float a0 = As[rm + g][kc * 8 + tg];
                float a1 = As[rm + g + 8][kc * 8 + tg];
                float a2 = As[rm + g][kc * 8 + tg + 4];
                float a3 = As[rm + g + 8][kc * 8 + tg + 4];
                unsigned ah0 = f2t(a0), ah1 = f2t(a1), ah2 = f2t(a2), ah3 = f2t(a3);
                unsigned al0 = f2t(a0 - __uint_as_float(ah0));
                unsigned al1 = f2t(a1 - __uint_as_float(ah1));
                unsigned al2 = f2t(a2 - __uint_as_float(ah2));
                unsigned al3 = f2t(a3 - __uint_as_float(ah3));
#pragma unroll
                for (int ni = 0; ni < 4; ni++) {
                    MMA(c[mi][ni], ah0, ah1, ah2, ah3, bh[ni][0], bh[ni][1]);
                    MMA(c[mi][ni], ah0, ah1, ah2, ah3, bl[ni][0], bl[ni][1]);
                    MMA(c[mi][ni], al0, al1, al2, al3, bh[ni][0], bh[ni][1]);
                }
            }
        }
        __syncthreads();
    }

    if (tid < 128) cs[tid] = 0.f;
    __syncthreads();

    float csl[4][2] = {};
#pragma unroll
    for (int mi = 0; mi < 4; mi++)
#pragma unroll
        for (int ni = 0; ni < 4; ni++) {
            int r1 = r0 + wm * 64 + mi * 16 + g;
            int r2 = r1 + 8;
            int m = mm0 + wn * 32 + ni * 8 + 2 * tg;
            float v0 = c[mi][ni][0] * 0.125f;
            float v1 = c[mi][ni][1] * 0.125f;
            float v2 = c[mi][ni][2] * 0.125f;
            float v3 = c[mi][ni][3] * 0.125f;
            v0 = (m >= 1 && m < r1) ? fmaxf(v0, 0.f) : 0.f;
            v1 = (m + 1 < r1) ? fmaxf(v1, 0.f) : 0.f;
            v2 = (m >= 1 && m < r2) ? fmaxf(v2, 0.f) : 0.f;
            v3 = (m + 1 < r2) ? fmaxf(v3, 0.f) : 0.f;
            *(float2*)&g_F[(size_t)(bb * SEQL + r1) * SEQL + m] = make_float2(v0, v1);
            *(float2*)&g_F[(size_t)(bb * SEQL + r2) * SEQL + m] = make_float2(v2, v3);
            csl[ni][0] += v0 + v2;
            csl[ni][1] += v1 + v3;
        }

#pragma unroll
    for (int ni = 0; ni < 4; ni++)
#pragma unroll
        for (int j = 0; j < 2; j++) {
            float v = csl[ni][j];
            v += __shfl_xor_sync(0xffffffffu, v, 4);
            v += __shfl_xor_sync(0xffffffffu, v, 8);
            v += __shfl_xor_sync(0xffffffffu, v, 16);
            csl[ni][j] = v;
        }
    if (g == 0) {
#pragma unroll
        for (int ni = 0; ni < 4; ni++) {
            atomicAdd(&cs[wn * 32 + ni * 8 + 2 * tg], csl[ni][0]);
            atomicAdd(&cs[wn * 32 + ni * 8 + 2 * tg + 1], csl[ni][1]);
        }
    }
    __syncthreads();
    if (tid < 128) g_P[pbase + tid] = cs[tid];
}

// ---------------- single scan pass ----------------
__global__ __launch_bounds__(256) void final_scan() {
    const int m = blockIdx.x * 256 + threadIdx.x;
    const int seg = blockIdx.y, b = blockIdx.z;
    float acc = 0.f;
    for (int s = 0; s < seg; s++)
        acc += g_P[(size_t)(b * NSEG + s) * SEQL + m];
    float* base = g_F + (size_t)(b * SEQL + seg * SEGROWS) * SEQL + m;
    const int r0 = seg * SEGROWS;
#pragma unroll 4
    for (int r = 0; r < SEGROWS; r++) {
        float c = (r0 + r > m) ? base[(size_t)r * SEQL] : 0.f;
        base[(size_t)r * SEQL] = acc;
        acc += c;
    }
}

// ---------------- flash attention: BM=64, 128 threads, cp.async K/V, exp2 softmax ----
#define ATTN_KSZ  (64 * 68)
#define ATTN_VSZ  (64 * 36)
#define ATTN_VHOFF (2 * ATTN_KSZ)
#define ATTN_VLOFF (2 * ATTN_KSZ + 2 * ATTN_VSZ)
#define ATTN_SMEM  ((2 * ATTN_KSZ + 4 * ATTN_VSZ) * 4)

__global__ __launch_bounds__(128) void attn_bf() {
    extern __shared__ unsigned sm[];
    const int b = blockIdx.z, h = blockIdx.y;
    const int qt = (int)gridDim.x - 1 - (int)blockIdx.x;
    const int q0 = qt * 64;
    const int tid = threadIdx.x, lane = tid & 31, w = tid >> 5;
    const int g = lane >> 2, tg = lane & 3;

    unsigned qa[8][4];
    const size_t qr1 = (size_t)(b * SEQL + q0 + w * 16 + g) * DMODEL + h * DHEAD;
    const size_t qr2 = qr1 + 8 * DMODEL;
#pragma unroll
    for (int kc = 0; kc < 8; kc++) {
        qa[kc][0] = g_Qt[qr1 + kc * 8 + tg];
        qa[kc][1] = g_Qt[qr2 + kc * 8 + tg];
        qa[kc][2] = g_Qt[qr1 + kc * 8 + tg + 4];
        qa[kc][3] = g_Qt[qr2 + kc * 8 + tg + 4];
    }

    float o[8][4] = {};
    float qm0 = -1e30f, qm1 = -1e30f, lsum0 = 0.f, lsum1 = 0.f;

    {
        const size_t kbase = (size_t)(b * SEQL) * DMODEL + h * DHEAD;
        const size_t vbase = (size_t)((b * NHEADS + h) * DHEAD) * (SEQL / 2);
#pragma unroll
        for (int t = 0; t < 8; t++) {
            int idx = tid + t * 128;
            int r = idx >> 4, c4 = (idx & 15) * 4;
            cpa16(&sm[r * 68 + c4], &g_Kt[kbase + (size_t)r * DMODEL + c4]);
        }
#pragma unroll
        for (int t = 0; t < 4; t++) {
            int idx = tid + t * 128;
            int r = idx >> 3, c4 = (idx & 7) * 4;
            cpa16(&sm[ATTN_VHOFF + r * 36 + c4], &g_Vth[vbase + (size_t)r * (SEQL / 2) + c4]);
            cpa16(&sm[ATTN_VLOFF + r * 36 + c4], &g_Vtl[vbase + (size_t)r * (SEQL / 2) + c4]);
        }
        CP_COMMIT();
    }

    for (int kt = 0; kt <= qt; kt++) {
        const int buf = kt & 1;
        const int m0 = kt * 64;
        if (kt < qt) {
            const int m0n = m0 + 64;
            const int nb = buf ^ 1;
            const size_t kbase = (size_t)(b * SEQL + m0n) * DMODEL + h * DHEAD;
            const size_t vbase = (size_t)((b * NHEADS + h) * DHEAD) * (SEQL / 2) + (m0n >> 1);
#pragma unroll
            for (int t = 0; t < 8; t++) {
                int idx = tid + t * 128;
                int r = idx >> 4, c4 = (idx & 15) * 4;
                cpa16(&sm[nb * ATTN_KSZ + r * 68 + c4], &g_Kt[kbase + (size_t)r * DMODEL + c4]);
            }
#pragma unroll
            for (int t = 0; t < 4; t++) {
                int idx = tid + t * 128;
                int r = idx >> 3, c4 = (idx & 7) * 4;
                cpa16(&sm[ATTN_VHOFF + nb * ATTN_VSZ + r * 36 + c4],
                      &g_Vth[vbase + (size_t)r * (SEQL / 2) + c4]);
                cpa16(&sm[ATTN_VLOFF + nb * ATTN_VSZ + r * 36 + c4],
                      &g_Vtl[vbase + (size_t)r * (SEQL / 2) + c4]);
            }
            CP_COMMIT();
            CP_WAIT1();
        } else {
            CP_WAIT0();
        }
        __syncthreads();

        const unsigned* sKt = sm + buf * ATTN_KSZ;
        const unsigned* sVh = sm + ATTN_VHOFF + buf * ATTN_VSZ;
        const unsigned* sVl = sm + ATTN_VLOFF + buf * ATTN_VSZ;

        float sc[8][4] = {};
#pragma unroll
        for (int kc = 0; kc < 8; kc++) {
#pragma unroll
            for (int ni = 0; ni < 8; ni++) {
                unsigned b0 = sKt[(ni * 8 + g) * 68 + kc * 8 + tg];
                unsigned b1 = sKt[(ni * 8 + g) * 68 + kc * 8 + tg + 4];
                MMA(sc[ni], qa[kc][0], qa[kc][1], qa[kc][2], qa[kc][3], b0, b1);
            }
        }

        const bool diag = (kt == qt);
        const int lr1 = w * 16 + g, lr2 = lr1 + 8;
        const size_t frow1 = (size_t)(b * SEQL + q0 + lr1) * SEQL + m0;
        const size_t frow2 = (size_t)(b * SEQL + q0 + lr2) * SEQL + m0;
        float mx0 = -1e30f, mx1 = -1e30f;
#pragma unroll
        for (int ni = 0; ni < 8; ni++) {
            int cl = ni * 8 + 2 * tg;
            float2 f1 = *(const float2*)&g_F[frow1 + cl];
            float2 f2 = *(const float2*)&g_F[frow2 + cl];
            // logits already in log2 domain (Qt pre-scaled by 0.125*log2e); F scaled here
            float v0 = fmaf(f1.x, -LOG2E, sc[ni][0]);
            float v1 = fmaf(f1.y, -LOG2E, sc[ni][1]);
            float v2 = fmaf(f2.x, -LOG2E, sc[ni][2]);
            float v3 = fmaf(f2.y, -LOG2E, sc[ni][3]);
            if (diag) {
                if (cl > lr1) v0 = -1e30f;
                if (cl + 1 > lr1) v1 = -1e30f;
                if (cl > lr2) v2 = -1e30f;
                if (cl + 1 > lr2) v3 = -1e30f;
            }
            sc[ni][0] = v0; sc[ni][1] = v1; sc[ni][2] = v2; sc[ni][3] = v3;
            mx0 = fmaxf(mx0, fmaxf(v0, v1));
            mx1 = fmaxf(mx1, fmaxf(v2, v3));
        }
        mx0 = fmaxf(mx0, __shfl_xor_sync(0xffffffffu, mx0, 1));
        mx0 = fmaxf(mx0, __shfl_xor_sync(0xffffffffu, mx0, 2));
        mx1 = fmaxf(mx1, __shfl_xor_sync(0xffffffffu, mx1, 1));
        mx1 = fmaxf(mx1, __shfl_xor_sync(0xffffffffu, mx1, 2));
        const float nm0 = fmaxf(qm0, mx0), nm1 = fmaxf(qm1, mx1);
        const float s0 = ex2(qm0 - nm0), s1 = ex2(qm1 - nm1);
        float ps0 = 0.f, ps1 = 0.f;
#pragma unroll
        for (int ni = 0; ni < 8; ni++) {
            float e0 = ex2(sc[ni][0] - nm0);
            float e1 = ex2(sc[ni][1] - nm0);
            float e2 = ex2(sc[ni][2] - nm1);
            float e3 = ex2(sc[ni][3] - nm1);
            sc[ni][0] = e0; sc[ni][1] = e1; sc[ni][2] = e2; sc[ni][3] = e3;
            ps0 += e0 + e1;
            ps1 += e2 + e3;
            o[ni][0] *= s0; o[ni][1] *= s0; o[ni][2] *= s1; o[ni][3] *= s1;
        }
        ps0 += __shfl_xor_sync(0xffffffffu, ps0, 1);
        ps0 += __shfl_xor_sync(0xffffffffu, ps0, 2);
        ps1 += __shfl_xor_sync(0xffffffffu, ps1, 1);
        ps1 += __shfl_xor_sync(0xffffffffu, ps1, 2);
        lsum0 = lsum0 * s0 + ps0;
        lsum1 = lsum1 * s1 + ps1;
        qm0 = nm0; qm1 = nm1;

#pragma unroll
        for (int kc2 = 0; kc2 < 4; kc2++) {
            unsigned ph0, pl0, ph1, pl1, ph2, pl2, ph3, pl3;
            bsplit(sc[kc2 * 2][0], sc[kc2 * 2][1], ph0, pl0);
            bsplit(sc[kc2 * 2][2], sc[kc2 * 2][3], ph1, pl1);
            bsplit(sc[kc2 * 2 + 1][0], sc[kc2 * 2 + 1][1], ph2, pl2);
            bsplit(sc[kc2 * 2 + 1][2], sc[kc2 * 2 + 1][3], ph3, pl3);
#pragma unroll
            for (int ni = 0; ni < 8; ni++) {
                int vb = (ni * 8 + g) * 36 + kc2 * 8 + tg;
                unsigned vh0 = sVh[vb], vh1 = sVh[vb + 4];
                unsigned vl0 = sVl[vb], vl1 = sVl[vb + 4];
                MMAB(o[ni], ph0, ph1, ph2, ph3, vh0, vh1);
                MMAB(o[ni], ph0, ph1, ph2, ph3, vl0, vl1);
                MMAB(o[ni], pl0, pl1, pl2, pl3, vh0, vh1);
            }
        }
        __syncthreads();
    }

    const float i0 = 1.0f / lsum0, i1 = 1.0f / lsum1;
    const size_t or1 = (size_t)(b * SEQL + q0 + w * 16 + g) * KP + h * 32;
    const size_t or2 = or1 + 8 * KP;
#pragma unroll
    for (int ni = 0; ni < 8; ni++) {
        unsigned hh, ll;
        bsplit(o[ni][0] * i0, o[ni][1] * i0, hh, ll);
        g_Oh[or1 + ni * 4 + tg] = hh;
        g_Ol[or1 + ni * 4 + tg] = ll;
        bsplit(o[ni][2] * i1, o[ni][3] * i1, hh, ll);
        g_Oh[or2 + ni * 4 + tg] = hh;
        g_Ol[or2 + ni * 4 + tg] = ll;
    }
}

// ---------------- launch ----------------
extern "C" void kernel_launch(void* const* d_in, const int* in_sizes, int n_in,
                              void* d_out, int out_size) {
    const float* X  = (const float*)d_in[0];
    const float* Wq = (const float*)d_in[1];
    const float* Wk = (const float*)d_in[2];
    const float* Wv = (const float*)d_in[3];
    const float* Wo = (const float*)d_in[4];
    const float* gq = (const float*)d_in[5];
    const float* bq = (const float*)d_in[6];
    const float* gk = (const float*)d_in[7];
    const float* bk = (const float*)d_in[8];
    float* out = (float*)d_out;

    float *pQ, *pK, *pV, *pXr, *pWr;
    unsigned *pWoh, *pWol, *pOh, *pOl;
    cudaGetSymbolAddress((void**)&pQ, g_Q);
    cudaGetSymbolAddress((void**)&pK, g_K);
    cudaGetSymbolAddress((void**)&pV, g_V);
    cudaGetSymbolAddress((void**)&pXr, g_Xr);
    cudaGetSymbolAddress((void**)&pWr, g_Wr);
    cudaGetSymbolAddress((void**)&pWoh, g_Woh);
    cudaGetSymbolAddress((void**)&pWol, g_Wol);
    cudaGetSymbolAddress((void**)&pOh, g_Oh);
    cudaGetSymbolAddress((void**)&pOl, g_Ol);

    cudaFuncSetAttribute(proj_fused, cudaFuncAttributeMaxDynamicSharedMemorySize, PROJ_SMEM);
    cudaFuncSetAttribute(gemm_bf3, cudaFuncAttributeMaxDynamicSharedMemorySize, PROJ_SMEM);
    cudaFuncSetAttribute(attn_bf, cudaFuncAttributeMaxDynamicSharedMemorySize, ATTN_SMEM);

    prepass<<<(PRE_TOT + 255) / 256, 256>>>(X, Wv, Wo, Wq, Wk);

    proj_fused<<<dim3(24, MR / 128), 256, PROJ_SMEM>>>(X, Wq, Wk, pXr, pWr, pQ, pK, pV);

    ln_qk<<<2 * MR, 256>>>(pQ, pK, gq, bq, gk, bk);

    head0_vt<<<dim3(16 + SEQL / 64, NSEG, BATCH), 256>>>();
    final_scan<<<dim3(SEQL / 256, NSEG, BATCH), 256>>>();

    attn_bf<<<dim3(SEQL / 64, NHEADS, BATCH), 128, ATTN_SMEM>>>();

    gemm_bf3<<<dim3(DMODEL / 128, MR / 128), 256, PROJ_SMEM>>>(pOh, pOl, pWoh, pWol, out,
                                                               MR, DMODEL, KP);
}